// round 13
// baseline (speedup 1.0000x reference)
#include <cuda_runtime.h>
#include <cuda_bf16.h>
#include <cstdint>

#define S_LEN 2048
#define HID   4096
#define NH    32
#define HD    128
#define ROPE  64
#define QR    1536
#define KVR   896
#define QDIM  192
#define EPS   1e-6f
#define SCALE_F 0.07216878364870322f  // 1/sqrt(192)

// ---------------- scratch ----------------
__device__ float g_qlat[S_LEN * QR];
__device__ float g_q[S_LEN * NH * QDIM];
__device__ float g_kv[S_LEN * (KVR + ROPE)];
__device__ float g_kvn[S_LEN * KVR];
__device__ float g_kvup[S_LEN * NH * 2 * HD];
__device__ float g_attn[S_LEN * NH * HD];

__device__ __nv_bfloat16 g_xh[S_LEN * HID];
__device__ __nv_bfloat16 g_xl[S_LEN * HID];
__device__ __nv_bfloat16 g_ah[S_LEN * HID];
__device__ __nv_bfloat16 g_al[S_LEN * HID];
__device__ __nv_bfloat16 g_wh[HID * HID];
__device__ __nv_bfloat16 g_wl[HID * HID];

__device__ __nv_bfloat16 g_qbh[(size_t)NH * S_LEN * QDIM];
__device__ __nv_bfloat16 g_qbl[(size_t)NH * S_LEN * QDIM];
__device__ __nv_bfloat16 g_kbh[(size_t)NH * S_LEN * QDIM];
__device__ __nv_bfloat16 g_kbl[(size_t)NH * S_LEN * QDIM];
__device__ __nv_bfloat16 g_vbh[(size_t)NH * HD * S_LEN];
__device__ __nv_bfloat16 g_vbl[(size_t)NH * HD * S_LEN];

// ---------------- helpers ----------------
#define MMA_BF16(c, a, b)                                                            \
    asm volatile(                                                                    \
        "mma.sync.aligned.m16n8k16.row.col.f32.bf16.bf16.f32 "                       \
        "{%0,%1,%2,%3}, {%4,%5,%6,%7}, {%8,%9}, {%0,%1,%2,%3};"                      \
        : "+f"(c[0]), "+f"(c[1]), "+f"(c[2]), "+f"(c[3])                             \
        : "r"(a[0]), "r"(a[1]), "r"(a[2]), "r"(a[3]), "r"(b[0]), "r"(b[1]))

#define LDMX4(r, p)                                                                  \
    asm volatile("ldmatrix.sync.aligned.m8n8.x4.shared.b16 {%0,%1,%2,%3}, [%4];"     \
                 : "=r"(r[0]), "=r"(r[1]), "=r"(r[2]), "=r"(r[3])                    \
                 : "r"((uint32_t)__cvta_generic_to_shared(p)))

__device__ __forceinline__ void cp16(void* dst_smem, const void* src) {
    uint32_t d = (uint32_t)__cvta_generic_to_shared(dst_smem);
    asm volatile("cp.async.cg.shared.global [%0], [%1], 16;" :: "r"(d), "l"(src));
}
#define CP_COMMIT() asm volatile("cp.async.commit_group;" ::: "memory")
#define CP_WAIT(n)  asm volatile("cp.async.wait_group %0;" :: "n"(n) : "memory")

// ---------------- fp32 -> (bf16 hi, bf16 lo) split ----------------
__global__ void split_kernel(const float* __restrict__ in, __nv_bfloat16* __restrict__ hi,
                             __nv_bfloat16* __restrict__ lo, int n) {
    int i = (blockIdx.x * blockDim.x + threadIdx.x) * 4;
    if (i >= n) return;
    float4 v = *(const float4*)(in + i);
    float vv[4] = {v.x, v.y, v.z, v.w};
    __nv_bfloat16 h[4], l[4];
#pragma unroll
    for (int j = 0; j < 4; j++) {
        h[j] = __float2bfloat16(vv[j]);
        l[j] = __float2bfloat16(vv[j] - __bfloat162float(h[j]));
    }
    __nv_bfloat162* hp = (__nv_bfloat162*)(hi + i);
    __nv_bfloat162* lp = (__nv_bfloat162*)(lo + i);
    hp[0] = __halves2bfloat162(h[0], h[1]);
    hp[1] = __halves2bfloat162(h[2], h[3]);
    lp[0] = __halves2bfloat162(l[0], l[1]);
    lp[1] = __halves2bfloat162(l[2], l[3]);
}

// ---------------- split-bf16 GEMM, 2-stage cp.async, 2 CTAs/SM (R8 + x4 B-ldmatrix) ----------------
#define LDSB 40
#define ST_TILE (128 * LDSB)
#define GEMM_SMEM (2 * 4 * ST_TILE * 2)   // 80 KB -> 2 CTAs/SM

__global__ void __launch_bounds__(256, 2) gemm_bf16x3(
    const __nv_bfloat16* __restrict__ Ah, const __nv_bfloat16* __restrict__ Al,
    const __nv_bfloat16* __restrict__ Bh, const __nv_bfloat16* __restrict__ Bl,
    float* __restrict__ C1, int ld1, float* __restrict__ C2, int ld2, int n1,
    int M, int N, int K) {
    extern __shared__ __nv_bfloat16 smx[];
    const int tid = threadIdx.x;
    const int wid = tid >> 5, lane = tid & 31;
    const int bm = blockIdx.y * 128;
    const int bn = blockIdx.x * 128;
    const int wm = (wid >> 2) * 64;
    const int wn = (wid & 3) * 32;

    const int lr = tid >> 1;
    const int lk = (tid & 1) * 16;
    const __nv_bfloat16* gAh = Ah + (size_t)(bm + lr) * K + lk;
    const __nv_bfloat16* gAl = Al + (size_t)(bm + lr) * K + lk;
    const int brow = min(bn + lr, N - 1);
    const __nv_bfloat16* gBh = Bh + (size_t)brow * K + lk;
    const __nv_bfloat16* gBl = Bl + (size_t)brow * K + lk;

    const int NS = K / 32;
    const int soff = lr * LDSB + lk;

    auto load_stage = [&](int s) {
        __nv_bfloat16* buf = smx + (s & 1) * 4 * ST_TILE;
        const int k0 = s * 32;
        cp16(buf + soff,                    gAh + k0);
        cp16(buf + soff + 8,                gAh + k0 + 8);
        cp16(buf + ST_TILE + soff,          gAl + k0);
        cp16(buf + ST_TILE + soff + 8,      gAl + k0 + 8);
        cp16(buf + 2 * ST_TILE + soff,      gBh + k0);
        cp16(buf + 2 * ST_TILE + soff + 8,  gBh + k0 + 8);
        cp16(buf + 3 * ST_TILE + soff,      gBl + k0);
        cp16(buf + 3 * ST_TILE + soff + 8,  gBl + k0 + 8);
        CP_COMMIT();
    };

    float acc[4][4][4];
#pragma unroll
    for (int i = 0; i < 4; i++)
#pragma unroll
        for (int j = 0; j < 4; j++)
#pragma unroll
            for (int r = 0; r < 4; r++) acc[i][j][r] = 0.f;

    load_stage(0);
    CP_WAIT(0);
    __syncthreads();

    const int ar = wm + (lane & 15);
    const int ac = (lane >> 4) * 8;
    const int br16 = wn + (lane & 15);   // B x4: 16 rows x both k-halves
    const int bkc = (lane >> 4) * 8;

    for (int s = 0; s < NS; s++) {
        if (s + 1 < NS) load_stage(s + 1);

        const __nv_bfloat16* buf = smx + (s & 1) * 4 * ST_TILE;
        const __nv_bfloat16* bAh = buf;
        const __nv_bfloat16* bAl = buf + ST_TILE;
        const __nv_bfloat16* bBh = buf + 2 * ST_TILE;
        const __nv_bfloat16* bBl = buf + 3 * ST_TILE;

#pragma unroll
        for (int kk = 0; kk < 32; kk += 16) {
            uint32_t a_h[4][4], a_l[4][4], b_h[4][2], b_l[4][2];
#pragma unroll
            for (int mi = 0; mi < 4; mi++) {
                LDMX4(a_h[mi], &bAh[(ar + mi * 16) * LDSB + kk + ac]);
                LDMX4(a_l[mi], &bAl[(ar + mi * 16) * LDSB + kk + ac]);
            }
#pragma unroll
            for (int g = 0; g < 2; g++) {
                uint32_t rh[4], rl[4];
                LDMX4(rh, &bBh[(br16 + g * 16) * LDSB + kk + bkc]);
                LDMX4(rl, &bBl[(br16 + g * 16) * LDSB + kk + bkc]);
                b_h[2 * g][0] = rh[0];     b_h[2 * g][1] = rh[2];
                b_h[2 * g + 1][0] = rh[1]; b_h[2 * g + 1][1] = rh[3];
                b_l[2 * g][0] = rl[0];     b_l[2 * g][1] = rl[2];
                b_l[2 * g + 1][0] = rl[1]; b_l[2 * g + 1][1] = rl[3];
            }
#pragma unroll
            for (int mi = 0; mi < 4; mi++)
#pragma unroll
                for (int nj = 0; nj < 4; nj++) MMA_BF16(acc[mi][nj], a_h[mi], b_h[nj]);
#pragma unroll
            for (int mi = 0; mi < 4; mi++)
#pragma unroll
                for (int nj = 0; nj < 4; nj++) MMA_BF16(acc[mi][nj], a_h[mi], b_l[nj]);
#pragma unroll
            for (int mi = 0; mi < 4; mi++)
#pragma unroll
                for (int nj = 0; nj < 4; nj++) MMA_BF16(acc[mi][nj], a_l[mi], b_h[nj]);
        }

        if (s + 1 < NS) {
            CP_WAIT(0);
            __syncthreads();
        }
    }

#pragma unroll
    for (int mi = 0; mi < 4; mi++) {
#pragma unroll
        for (int nj = 0; nj < 4; nj++) {
            const int row0 = bm + wm + mi * 16 + (lane >> 2);
            const int col = bn + wn + nj * 8 + (lane & 3) * 2;
            if (col < N) {
                if (col < n1) {
                    C1[(size_t)row0 * ld1 + col]           = acc[mi][nj][0];
                    C1[(size_t)row0 * ld1 + col + 1]       = acc[mi][nj][1];
                    C1[(size_t)(row0 + 8) * ld1 + col]     = acc[mi][nj][2];
                    C1[(size_t)(row0 + 8) * ld1 + col + 1] = acc[mi][nj][3];
                } else {
                    const int c2 = col - n1;
                    C2[(size_t)row0 * ld2 + c2]           = acc[mi][nj][0];
                    C2[(size_t)row0 * ld2 + c2 + 1]       = acc[mi][nj][1];
                    C2[(size_t)(row0 + 8) * ld2 + c2]     = acc[mi][nj][2];
                    C2[(size_t)(row0 + 8) * ld2 + c2 + 1] = acc[mi][nj][3];
                }
            }
        }
    }
}

// ---------------- RMSNorm ----------------
__global__ void rmsnorm_kernel(const float* __restrict__ in, const float* __restrict__ w,
                               float* __restrict__ out, int n, int in_stride, int out_stride) {
    const int row = blockIdx.x;
    const float* p = in + (size_t)row * in_stride;
    float ss = 0.f;
    for (int i = threadIdx.x; i < n; i += blockDim.x) {
        float v = p[i];
        ss += v * v;
    }
    __shared__ float red[8];
#pragma unroll
    for (int o = 16; o > 0; o >>= 1) ss += __shfl_xor_sync(0xffffffff, ss, o);
    if ((threadIdx.x & 31) == 0) red[threadIdx.x >> 5] = ss;
    __syncthreads();
    if (threadIdx.x < 8) {
        float v = red[threadIdx.x];
#pragma unroll
        for (int o = 4; o > 0; o >>= 1) v += __shfl_xor_sync(0xff, v, o);
        if (threadIdx.x == 0) red[0] = v;
    }
    __syncthreads();
    const float scale = rsqrtf(red[0] / (float)n + EPS);
    float* q = out + (size_t)row * out_stride;
    for (int i = threadIdx.x; i < n; i += blockDim.x) q[i] = p[i] * scale * w[i];
}

// ---------------- RoPE + pack Q/K bf16 hi/lo [h][s][d] ----------------
__global__ void rope_pack_bf16(const float* __restrict__ q, const float* __restrict__ kv,
                               const float* __restrict__ kvup,
                               const float* __restrict__ cosT, const float* __restrict__ sinT,
                               __nv_bfloat16* __restrict__ qh, __nv_bfloat16* __restrict__ ql,
                               __nv_bfloat16* __restrict__ kh, __nv_bfloat16* __restrict__ kl) {
    const int s = blockIdx.x;
    const int h = blockIdx.y;
    const int d = threadIdx.x;

    float qv, kvv;
    if (d < ROPE) {
        const float c = cosT[s * ROPE + d];
        const float sn = sinT[s * ROPE + d];
        const int dro = (d < 32) ? d + 32 : d - 32;
        const float sgn = (d < 32) ? -1.f : 1.f;
        const float xq = q[(size_t)s * (NH * QDIM) + h * QDIM + d];
        const float xqo = q[(size_t)s * (NH * QDIM) + h * QDIM + dro];
        qv = xq * c + sgn * xqo * sn;
        const float xk = kv[(size_t)s * (KVR + ROPE) + KVR + d];
        const float xko = kv[(size_t)s * (KVR + ROPE) + KVR + dro];
        kvv = xk * c + sgn * xko * sn;
    } else {
        qv = q[(size_t)s * (NH * QDIM) + h * QDIM + d];
        kvv = kvup[(size_t)s * (NH * 2 * HD) + h * (2 * HD) + (d - ROPE)];
    }
    qv *= SCALE_F;
    const size_t o = ((size_t)h * S_LEN + s) * QDIM + d;
    __nv_bfloat16 hq = __float2bfloat16(qv);
    qh[o] = hq;
    ql[o] = __float2bfloat16(qv - __bfloat162float(hq));
    __nv_bfloat16 hk = __float2bfloat16(kvv);
    kh[o] = hk;
    kl[o] = __float2bfloat16(kvv - __bfloat162float(hk));
}

// ---------------- V transpose-pack ----------------
__global__ void v_pack(const float* __restrict__ kvup,
                       __nv_bfloat16* __restrict__ vh, __nv_bfloat16* __restrict__ vl) {
    __shared__ float tile[32][33];
    const int s0 = blockIdx.x * 32, d0 = blockIdx.y * 32, h = blockIdx.z;
    const int tx = threadIdx.x, ty = threadIdx.y;
#pragma unroll
    for (int i = 0; i < 4; i++) {
        const int s = s0 + ty + i * 8;
        tile[ty + i * 8][tx] = kvup[(size_t)s * (NH * 2 * HD) + h * (2 * HD) + HD + d0 + tx];
    }
    __syncthreads();
#pragma unroll
    for (int i = 0; i < 4; i++) {
        const int dv = d0 + ty + i * 8;
        const float v = tile[tx][ty + i * 8];
        __nv_bfloat16 hv = __float2bfloat16(v);
        const size_t o = ((size_t)(h * HD + dv)) * S_LEN + s0 + tx;
        vh[o] = hv;
        vl[o] = __float2bfloat16(v - __bfloat162float(hv));
    }
}

// ---------------- tensor-core flash attention (validated R5/R8) ----------------
#define QSTR 200
#define VSTR 72
#define ATTN_SMEM ((128 * QSTR * 2 + 64 * QSTR * 2 + 128 * VSTR * 2) * 2)

__device__ __forceinline__ uint32_t pack_bf2(float a, float b) {
    __nv_bfloat162 t = __floats2bfloat162_rn(a, b);
    return *(uint32_t*)&t;
}

__global__ void __launch_bounds__(256) attn_mma(
    const __nv_bfloat16* __restrict__ qh, const __nv_bfloat16* __restrict__ ql,
    const __nv_bfloat16* __restrict__ kh, const __nv_bfloat16* __restrict__ kl,
    const __nv_bfloat16* __restrict__ vh, const __nv_bfloat16* __restrict__ vl,
    float* __restrict__ outp) {
    extern __shared__ __nv_bfloat16 sm[];
    __nv_bfloat16* sQh = sm;
    __nv_bfloat16* sQl = sQh + 128 * QSTR;
    __nv_bfloat16* sKh = sQl + 128 * QSTR;
    __nv_bfloat16* sKl = sKh + 64 * QSTR;
    __nv_bfloat16* sVh = sKl + 64 * QSTR;
    __nv_bfloat16* sVl = sVh + 128 * VSTR;

    const int qb = (gridDim.x - 1 - blockIdx.x) * 128;
    const int h = blockIdx.y;
    const int tid = threadIdx.x;
    const int wid = tid >> 5, lane = tid & 31;

    const __nv_bfloat16* qhb = qh + ((size_t)h * S_LEN + qb) * QDIM;
    const __nv_bfloat16* qlb = ql + ((size_t)h * S_LEN + qb) * QDIM;
    for (int i = tid; i < 128 * 24; i += 256) {
        const int r = i / 24, c = (i % 24) * 8;
        *(uint4*)&sQh[r * QSTR + c] = *(const uint4*)&qhb[(size_t)r * QDIM + c];
        *(uint4*)&sQl[r * QSTR + c] = *(const uint4*)&qlb[(size_t)r * QDIM + c];
    }

    float o_r[16][4];
#pragma unroll
    for (int n = 0; n < 16; n++)
#pragma unroll
        for (int r = 0; r < 4; r++) o_r[n][r] = 0.f;
    float m0 = -1e30f, m1 = -1e30f, l0 = 0.f, l1 = 0.f;

    const int r0w = qb + wid * 16 + (lane >> 2);
    const int r1w = r0w + 8;

    const __nv_bfloat16* khb = kh + (size_t)h * S_LEN * QDIM;
    const __nv_bfloat16* klb = kl + (size_t)h * S_LEN * QDIM;
    const __nv_bfloat16* vhb = vh + (size_t)h * HD * S_LEN;
    const __nv_bfloat16* vlb = vl + (size_t)h * HD * S_LEN;

    const int ntiles = qb / 64 + 2;
    for (int t = 0; t < ntiles; t++) {
        const int kb = t * 64;
        __syncthreads();
        for (int i = tid; i < 64 * 24; i += 256) {
            const int r = i / 24, c = (i % 24) * 8;
            *(uint4*)&sKh[r * QSTR + c] = *(const uint4*)&khb[(size_t)(kb + r) * QDIM + c];
            *(uint4*)&sKl[r * QSTR + c] = *(const uint4*)&klb[(size_t)(kb + r) * QDIM + c];
        }
        for (int i = tid; i < 128 * 8; i += 256) {
            const int r = i / 8, c = (i % 8) * 8;
            *(uint4*)&sVh[r * VSTR + c] = *(const uint4*)&vhb[(size_t)r * S_LEN + kb + c];
            *(uint4*)&sVl[r * VSTR + c] = *(const uint4*)&vlb[(size_t)r * S_LEN + kb + c];
        }
        __syncthreads();

        if (kb > qb + wid * 16 + 15) continue;

        float sc[8][4];
#pragma unroll
        for (int j = 0; j < 8; j++)
#pragma unroll
            for (int r = 0; r < 4; r++) sc[j][r] = 0.f;

        const int arow = wid * 16 + (lane & 15);
        const int xcol = (lane >> 4) * 8;
#pragma unroll
        for (int ks = 0; ks < 12; ks++) {
            uint32_t aH[4], aL[4];
            LDMX4(aH, &sQh[arow * QSTR + ks * 16 + xcol]);
            LDMX4(aL, &sQl[arow * QSTR + ks * 16 + xcol]);
#pragma unroll
            for (int g = 0; g < 4; g++) {
                uint32_t rh[4], rl[4];
                LDMX4(rh, &sKh[(g * 16 + (lane & 15)) * QSTR + ks * 16 + xcol]);
                LDMX4(rl, &sKl[(g * 16 + (lane & 15)) * QSTR + ks * 16 + xcol]);
                uint32_t bh0[2] = {rh[0], rh[2]}, bh1[2] = {rh[1], rh[3]};
                uint32_t bl0[2] = {rl[0], rl[2]}, bl1[2] = {rl[1], rl[3]};
                MMA_BF16(sc[2 * g],     aH, bh0);
                MMA_BF16(sc[2 * g],     aH, bl0);
                MMA_BF16(sc[2 * g],     aL, bh0);
                MMA_BF16(sc[2 * g + 1], aH, bh1);
                MMA_BF16(sc[2 * g + 1], aH, bl1);
                MMA_BF16(sc[2 * g + 1], aL, bh1);
            }
        }

        if (kb + 63 > r0w) {
#pragma unroll
            for (int j = 0; j < 8; j++) {
                const int colg = kb + j * 8 + (lane & 3) * 2;
                if (colg     > r0w) sc[j][0] = -1e30f;
                if (colg + 1 > r0w) sc[j][1] = -1e30f;
                if (colg     > r1w) sc[j][2] = -1e30f;
                if (colg + 1 > r1w) sc[j][3] = -1e30f;
            }
        }

        float mx0 = -1e30f, mx1 = -1e30f;
#pragma unroll
        for (int j = 0; j < 8; j++) {
            mx0 = fmaxf(mx0, fmaxf(sc[j][0], sc[j][1]));
            mx1 = fmaxf(mx1, fmaxf(sc[j][2], sc[j][3]));
        }
        mx0 = fmaxf(mx0, __shfl_xor_sync(0xffffffff, mx0, 1));
        mx0 = fmaxf(mx0, __shfl_xor_sync(0xffffffff, mx0, 2));
        mx1 = fmaxf(mx1, __shfl_xor_sync(0xffffffff, mx1, 1));
        mx1 = fmaxf(mx1, __shfl_xor_sync(0xffffffff, mx1, 2));
        const float mn0 = fmaxf(m0, mx0), mn1 = fmaxf(m1, mx1);
        const float al0 = __expf(m0 - mn0), al1 = __expf(m1 - mn1);
        float rs0 = 0.f, rs1 = 0.f;
#pragma unroll
        for (int j = 0; j < 8; j++) {
            sc[j][0] = __expf(sc[j][0] - mn0);
            sc[j][1] = __expf(sc[j][1] - mn0);
            sc[j][2] = __expf(sc[j][2] - mn1);
            sc[j][3] = __expf(sc[j][3] - mn1);
            rs0 += sc[j][0] + sc[j][1];
            rs1 += sc[j][2] + sc[j][3];
        }
        rs0 += __shfl_xor_sync(0xffffffff, rs0, 1);
        rs0 += __shfl_xor_sync(0xffffffff, rs0, 2);
        rs1 += __shfl_xor_sync(0xffffffff, rs1, 1);
        rs1 += __shfl_xor_sync(0xffffffff, rs1, 2);
        l0 = l0 * al0 + rs0;
        l1 = l1 * al1 + rs1;
        m0 = mn0;
        m1 = mn1;
#pragma unroll
        for (int n = 0; n < 16; n++) {
            o_r[n][0] *= al0; o_r[n][1] *= al0;
            o_r[n][2] *= al1; o_r[n][3] *= al1;
        }

#pragma unroll
        for (int ku = 0; ku < 4; ku++) {
            float ph[8], pl[8];
#pragma unroll
            for (int e = 0; e < 4; e++) {
                const float v0 = sc[2 * ku][e], v1 = sc[2 * ku + 1][e];
                const float h0 = __bfloat162float(__float2bfloat16(v0));
                const float h1 = __bfloat162float(__float2bfloat16(v1));
                ph[e] = h0;     pl[e] = v0 - h0;
                ph[4 + e] = h1; pl[4 + e] = v1 - h1;
            }
            uint32_t aPh[4], aPl[4];
            aPh[0] = pack_bf2(ph[0], ph[1]);  aPl[0] = pack_bf2(pl[0], pl[1]);
            aPh[1] = pack_bf2(ph[2], ph[3]);  aPl[1] = pack_bf2(pl[2], pl[3]);
            aPh[2] = pack_bf2(ph[4], ph[5]);  aPl[2] = pack_bf2(pl[4], pl[5]);
            aPh[3] = pack_bf2(ph[6], ph[7]);  aPl[3] = pack_bf2(pl[6], pl[7]);
            const int vc = ku * 16 + xcol;
#pragma unroll
            for (int g = 0; g < 8; g++) {
                uint32_t rh[4], rl[4];
                LDMX4(rh, &sVh[(g * 16 + (lane & 15)) * VSTR + vc]);
                LDMX4(rl, &sVl[(g * 16 + (lane & 15)) * VSTR + vc]);
                uint32_t bh0[2] = {rh[0], rh[2]}, bh1[2] = {rh[1], rh[3]};
                uint32_t bl0[2] = {rl[0], rl[2]}, bl1[2] = {rl[1], rl[3]};
                MMA_BF16(o_r[2 * g],     aPh, bh0);
                MMA_BF16(o_r[2 * g],     aPh, bl0);
                MMA_BF16(o_r[2 * g],     aPl, bh0);
                MMA_BF16(o_r[2 * g + 1], aPh, bh1);
                MMA_BF16(o_r[2 * g + 1], aPh, bl1);
                MMA_BF16(o_r[2 * g + 1], aPl, bh1);
            }
        }
    }

    const float inv0 = 1.f / l0, inv1 = 1.f / l1;
#pragma unroll
    for (int n = 0; n < 16; n++) {
        const int col = h * HD + n * 8 + (lane & 3) * 2;
        outp[(size_t)r0w * (NH * HD) + col]     = o_r[n][0] * inv0;
        outp[(size_t)r0w * (NH * HD) + col + 1] = o_r[n][1] * inv0;
        outp[(size_t)r1w * (NH * HD) + col]     = o_r[n][2] * inv1;
        outp[(size_t)r1w * (NH * HD) + col + 1] = o_r[n][3] * inv1;
    }
}

// ---------------- launch ----------------
static inline void split_launch(const float* in, __nv_bfloat16* hi, __nv_bfloat16* lo, int n) {
    split_kernel<<<(n / 4 + 255) / 256, 256>>>(in, hi, lo, n);
}
static inline void gemm_launch(const __nv_bfloat16* ah, const __nv_bfloat16* al,
                               const __nv_bfloat16* bh, const __nv_bfloat16* bl,
                               float* c1, int ld1, float* c2, int ld2, int n1,
                               int M, int N, int K) {
    gemm_bf16x3<<<dim3((N + 127) / 128, M / 128), 256, GEMM_SMEM>>>(
        ah, al, bh, bl, c1, ld1, c2, ld2, n1, M, N, K);
}

extern "C" void kernel_launch(void* const* d_in, const int* in_sizes, int n_in,
                              void* d_out, int out_size) {
    const float* x          = (const float*)d_in[0];
    const float* cosp       = (const float*)d_in[1];
    const float* sinp       = (const float*)d_in[2];
    const float* q_a_w      = (const float*)d_in[3];
    const float* q_a_norm_w = (const float*)d_in[4];
    const float* q_b_w      = (const float*)d_in[5];
    const float* kv_a_w     = (const float*)d_in[6];
    const float* kv_a_norm_w= (const float*)d_in[7];
    const float* kv_b_w     = (const float*)d_in[8];
    const float* o_w        = (const float*)d_in[9];

    float *qlat, *q, *kv, *kvn, *kvup, *attn;
    __nv_bfloat16 *xh, *xl, *ah, *al, *wh, *wl;
    __nv_bfloat16 *qbh, *qbl, *kbh, *kbl, *vbh, *vbl;
    cudaGetSymbolAddress((void**)&qlat, g_qlat);
    cudaGetSymbolAddress((void**)&q,    g_q);
    cudaGetSymbolAddress((void**)&kv,   g_kv);
    cudaGetSymbolAddress((void**)&kvn,  g_kvn);
    cudaGetSymbolAddress((void**)&kvup, g_kvup);
    cudaGetSymbolAddress((void**)&attn, g_attn);
    cudaGetSymbolAddress((void**)&xh,   g_xh);
    cudaGetSymbolAddress((void**)&xl,   g_xl);
    cudaGetSymbolAddress((void**)&ah,   g_ah);
    cudaGetSymbolAddress((void**)&al,   g_al);
    cudaGetSymbolAddress((void**)&wh,   g_wh);
    cudaGetSymbolAddress((void**)&wl,   g_wl);
    cudaGetSymbolAddress((void**)&qbh,  g_qbh);
    cudaGetSymbolAddress((void**)&qbl,  g_qbl);
    cudaGetSymbolAddress((void**)&kbh,  g_kbh);
    cudaGetSymbolAddress((void**)&kbl,  g_kbl);
    cudaGetSymbolAddress((void**)&vbh,  g_vbh);
    cudaGetSymbolAddress((void**)&vbl,  g_vbl);

    cudaFuncSetAttribute(gemm_bf16x3, cudaFuncAttributeMaxDynamicSharedMemorySize, GEMM_SMEM);
    cudaFuncSetAttribute(attn_mma, cudaFuncAttributeMaxDynamicSharedMemorySize, ATTN_SMEM);

    split_launch(x, xh, xl, S_LEN * HID);

    // 1+4 fused) [qlat | kv] = x @ [q_a_w ; kv_a_w]^T
    split_launch(q_a_w, wh, wl, QR * HID);
    split_launch(kv_a_w, wh + (size_t)QR * HID, wl + (size_t)QR * HID, (KVR + ROPE) * HID);
    gemm_launch(xh, xl, wh, wl, qlat, QR, kv, KVR + ROPE, QR,
                S_LEN, QR + KVR + ROPE, HID);
    // 2) rmsnorm q_lat
    rmsnorm_kernel<<<S_LEN, 256>>>(qlat, q_a_norm_w, qlat, QR, QR, QR);
    // 5) rmsnorm kv -> kvn
    rmsnorm_kernel<<<S_LEN, 256>>>(kv, kv_a_norm_w, kvn, KVR, KVR + ROPE, KVR);
    // 3) q = q_lat @ q_b_w^T
    split_launch(qlat, ah, al, S_LEN * QR);
    split_launch(q_b_w, wh, wl, NH * QDIM * QR);
    gemm_launch(ah, al, wh, wl, q, NH * QDIM, q, NH * QDIM, NH * QDIM,
                S_LEN, NH * QDIM, QR);
    // 6) kv_up = kvn @ kv_b_w^T
    split_launch(kvn, ah, al, S_LEN * KVR);
    split_launch(kv_b_w, wh, wl, NH * 2 * HD * KVR);
    gemm_launch(ah, al, wh, wl, kvup, NH * 2 * HD, kvup, NH * 2 * HD, NH * 2 * HD,
                S_LEN, NH * 2 * HD, KVR);
    // 7) rope + packs
    rope_pack_bf16<<<dim3(S_LEN, NH), QDIM>>>(q, kv, kvup, cosp, sinp, qbh, qbl, kbh, kbl);
    v_pack<<<dim3(S_LEN / 32, HD / 32, NH), dim3(32, 8)>>>(kvup, vbh, vbl);
    // 8) attention
    attn_mma<<<dim3(S_LEN / 128, NH), 256, ATTN_SMEM>>>(qbh, qbl, kbh, kbl, vbh, vbl, attn);
    // 9) out = attn @ o_w^T
    split_launch(attn, ah, al, S_LEN * NH * HD);
    split_launch(o_w, wh, wl, HID * NH * HD);
    gemm_launch(ah, al, wh, wl, (float*)d_out, HID, (float*)d_out, HID, HID,
                S_LEN, HID, HID);
}

// round 14
// speedup vs baseline: 1.1373x; 1.1373x over previous
#include <cuda_runtime.h>
#include <cuda_bf16.h>
#include <cstdint>

#define S_LEN 2048
#define HID   4096
#define NH    32
#define HD    128
#define ROPE  64
#define QR    1536
#define KVR   896
#define QDIM  192
#define EPS   1e-6f
#define SCALE_F 0.07216878364870322f  // 1/sqrt(192)

// ---------------- scratch ----------------
__device__ float g_qlat[S_LEN * QR];
__device__ float g_q[S_LEN * NH * QDIM];
__device__ float g_kv[S_LEN * (KVR + ROPE)];
__device__ float g_kvn[S_LEN * KVR];
__device__ float g_kvup[S_LEN * NH * 2 * HD];
__device__ float g_attn[S_LEN * NH * HD];
__device__ float g_part[2 * (size_t)S_LEN * (QR + KVR + ROPE)];  // fused K-split partials

__device__ __nv_bfloat16 g_xh[S_LEN * HID];
__device__ __nv_bfloat16 g_xl[S_LEN * HID];
__device__ __nv_bfloat16 g_ah[S_LEN * HID];
__device__ __nv_bfloat16 g_al[S_LEN * HID];
__device__ __nv_bfloat16 g_wh[HID * HID];
__device__ __nv_bfloat16 g_wl[HID * HID];

__device__ __nv_bfloat16 g_qbh[(size_t)NH * S_LEN * QDIM];
__device__ __nv_bfloat16 g_qbl[(size_t)NH * S_LEN * QDIM];
__device__ __nv_bfloat16 g_kbh[(size_t)NH * S_LEN * QDIM];
__device__ __nv_bfloat16 g_kbl[(size_t)NH * S_LEN * QDIM];
__device__ __nv_bfloat16 g_vbh[(size_t)NH * HD * S_LEN];
__device__ __nv_bfloat16 g_vbl[(size_t)NH * HD * S_LEN];

// ---------------- helpers ----------------
#define MMA_BF16(c, a, b)                                                            \
    asm volatile(                                                                    \
        "mma.sync.aligned.m16n8k16.row.col.f32.bf16.bf16.f32 "                       \
        "{%0,%1,%2,%3}, {%4,%5,%6,%7}, {%8,%9}, {%0,%1,%2,%3};"                      \
        : "+f"(c[0]), "+f"(c[1]), "+f"(c[2]), "+f"(c[3])                             \
        : "r"(a[0]), "r"(a[1]), "r"(a[2]), "r"(a[3]), "r"(b[0]), "r"(b[1]))

#define LDMX4(r, p)                                                                  \
    asm volatile("ldmatrix.sync.aligned.m8n8.x4.shared.b16 {%0,%1,%2,%3}, [%4];"     \
                 : "=r"(r[0]), "=r"(r[1]), "=r"(r[2]), "=r"(r[3])                    \
                 : "r"((uint32_t)__cvta_generic_to_shared(p)))

#define LDMX2(r, p)                                                                  \
    asm volatile("ldmatrix.sync.aligned.m8n8.x2.shared.b16 {%0,%1}, [%2];"           \
                 : "=r"(r[0]), "=r"(r[1])                                            \
                 : "r"((uint32_t)__cvta_generic_to_shared(p)))

__device__ __forceinline__ void cp16(void* dst_smem, const void* src) {
    uint32_t d = (uint32_t)__cvta_generic_to_shared(dst_smem);
    asm volatile("cp.async.cg.shared.global [%0], [%1], 16;" :: "r"(d), "l"(src));
}
#define CP_COMMIT() asm volatile("cp.async.commit_group;" ::: "memory")
#define CP_WAIT(n)  asm volatile("cp.async.wait_group %0;" :: "n"(n) : "memory")

// ---------------- fp32 -> (bf16 hi, bf16 lo) split ----------------
__global__ void split_kernel(const float* __restrict__ in, __nv_bfloat16* __restrict__ hi,
                             __nv_bfloat16* __restrict__ lo, int n) {
    int i = (blockIdx.x * blockDim.x + threadIdx.x) * 4;
    if (i >= n) return;
    float4 v = *(const float4*)(in + i);
    float vv[4] = {v.x, v.y, v.z, v.w};
    __nv_bfloat16 h[4], l[4];
#pragma unroll
    for (int j = 0; j < 4; j++) {
        h[j] = __float2bfloat16(vv[j]);
        l[j] = __float2bfloat16(vv[j] - __bfloat162float(h[j]));
    }
    __nv_bfloat162* hp = (__nv_bfloat162*)(hi + i);
    __nv_bfloat162* lp = (__nv_bfloat162*)(lo + i);
    hp[0] = __halves2bfloat162(h[0], h[1]);
    hp[1] = __halves2bfloat162(h[2], h[3]);
    lp[0] = __halves2bfloat162(l[0], l[1]);
    lp[1] = __halves2bfloat162(l[2], l[3]);
}

// ---------------- split-bf16 GEMM (R8 exact core: x2 B-ldmatrix) + optional K-split ----------------
#define LDSB 40
#define ST_TILE (128 * LDSB)
#define GEMM_SMEM (2 * 4 * ST_TILE * 2)   // 80 KB -> 2 CTAs/SM

__global__ void __launch_bounds__(256, 2) gemm_bf16x3(
    const __nv_bfloat16* __restrict__ Ah, const __nv_bfloat16* __restrict__ Al,
    const __nv_bfloat16* __restrict__ Bh, const __nv_bfloat16* __restrict__ Bl,
    float* __restrict__ C1, int ld1, float* __restrict__ C2, int ld2, int n1,
    float* __restrict__ Cp, int M, int N, int K) {
    extern __shared__ __nv_bfloat16 smx[];
    const int tid = threadIdx.x;
    const int wid = tid >> 5, lane = tid & 31;
    const int bm = blockIdx.y * 128;
    const int bn = blockIdx.x * 128;
    const int wm = (wid >> 2) * 64;
    const int wn = (wid & 3) * 32;

    const int Ksub = K / gridDim.z;
    const int Koff = blockIdx.z * Ksub;

    const int lr = tid >> 1;
    const int lk = (tid & 1) * 16;
    const __nv_bfloat16* gAh = Ah + (size_t)(bm + lr) * K + Koff + lk;
    const __nv_bfloat16* gAl = Al + (size_t)(bm + lr) * K + Koff + lk;
    const int brow = min(bn + lr, N - 1);
    const __nv_bfloat16* gBh = Bh + (size_t)brow * K + Koff + lk;
    const __nv_bfloat16* gBl = Bl + (size_t)brow * K + Koff + lk;

    const int NS = Ksub / 32;
    const int soff = lr * LDSB + lk;

    auto load_stage = [&](int s) {
        __nv_bfloat16* buf = smx + (s & 1) * 4 * ST_TILE;
        const int k0 = s * 32;
        cp16(buf + soff,                    gAh + k0);
        cp16(buf + soff + 8,                gAh + k0 + 8);
        cp16(buf + ST_TILE + soff,          gAl + k0);
        cp16(buf + ST_TILE + soff + 8,      gAl + k0 + 8);
        cp16(buf + 2 * ST_TILE + soff,      gBh + k0);
        cp16(buf + 2 * ST_TILE + soff + 8,  gBh + k0 + 8);
        cp16(buf + 3 * ST_TILE + soff,      gBl + k0);
        cp16(buf + 3 * ST_TILE + soff + 8,  gBl + k0 + 8);
        CP_COMMIT();
    };

    float acc[4][4][4];
#pragma unroll
    for (int i = 0; i < 4; i++)
#pragma unroll
        for (int j = 0; j < 4; j++)
#pragma unroll
            for (int r = 0; r < 4; r++) acc[i][j][r] = 0.f;

    load_stage(0);
    CP_WAIT(0);
    __syncthreads();

    const int ar = wm + (lane & 15);
    const int ac = (lane >> 4) * 8;
    const int br = wn + (lane & 7);
    const int bc = ((lane >> 3) & 1) * 8;

    for (int s = 0; s < NS; s++) {
        if (s + 1 < NS) load_stage(s + 1);

        const __nv_bfloat16* buf = smx + (s & 1) * 4 * ST_TILE;
        const __nv_bfloat16* bAh = buf;
        const __nv_bfloat16* bAl = buf + ST_TILE;
        const __nv_bfloat16* bBh = buf + 2 * ST_TILE;
        const __nv_bfloat16* bBl = buf + 3 * ST_TILE;

#pragma unroll
        for (int kk = 0; kk < 32; kk += 16) {
            uint32_t a_h[4][4], a_l[4][4], b_h[4][2], b_l[4][2];
#pragma unroll
            for (int mi = 0; mi < 4; mi++) {
                LDMX4(a_h[mi], &bAh[(ar + mi * 16) * LDSB + kk + ac]);
                LDMX4(a_l[mi], &bAl[(ar + mi * 16) * LDSB + kk + ac]);
            }
#pragma unroll
            for (int nj = 0; nj < 4; nj++) {
                LDMX2(b_h[nj], &bBh[(br + nj * 8) * LDSB + kk + bc]);
                LDMX2(b_l[nj], &bBl[(br + nj * 8) * LDSB + kk + bc]);
            }
#pragma unroll
            for (int mi = 0; mi < 4; mi++)
#pragma unroll
                for (int nj = 0; nj < 4; nj++) MMA_BF16(acc[mi][nj], a_h[mi], b_h[nj]);
#pragma unroll
            for (int mi = 0; mi < 4; mi++)
#pragma unroll
                for (int nj = 0; nj < 4; nj++) MMA_BF16(acc[mi][nj], a_h[mi], b_l[nj]);
#pragma unroll
            for (int mi = 0; mi < 4; mi++)
#pragma unroll
                for (int nj = 0; nj < 4; nj++) MMA_BF16(acc[mi][nj], a_l[mi], b_h[nj]);
        }

        if (s + 1 < NS) {
            CP_WAIT(0);
            __syncthreads();
        }
    }

    if (gridDim.z > 1) {
        float* dst = Cp + (size_t)blockIdx.z * M * N;
#pragma unroll
        for (int mi = 0; mi < 4; mi++) {
#pragma unroll
            for (int nj = 0; nj < 4; nj++) {
                const int row0 = bm + wm + mi * 16 + (lane >> 2);
                const int col = bn + wn + nj * 8 + (lane & 3) * 2;
                if (col < N) {
                    dst[(size_t)row0 * N + col]           = acc[mi][nj][0];
                    dst[(size_t)row0 * N + col + 1]       = acc[mi][nj][1];
                    dst[(size_t)(row0 + 8) * N + col]     = acc[mi][nj][2];
                    dst[(size_t)(row0 + 8) * N + col + 1] = acc[mi][nj][3];
                }
            }
        }
        return;
    }

#pragma unroll
    for (int mi = 0; mi < 4; mi++) {
#pragma unroll
        for (int nj = 0; nj < 4; nj++) {
            const int row0 = bm + wm + mi * 16 + (lane >> 2);
            const int col = bn + wn + nj * 8 + (lane & 3) * 2;
            if (col < N) {
                if (col < n1) {
                    C1[(size_t)row0 * ld1 + col]           = acc[mi][nj][0];
                    C1[(size_t)row0 * ld1 + col + 1]       = acc[mi][nj][1];
                    C1[(size_t)(row0 + 8) * ld1 + col]     = acc[mi][nj][2];
                    C1[(size_t)(row0 + 8) * ld1 + col + 1] = acc[mi][nj][3];
                } else {
                    const int c2 = col - n1;
                    C2[(size_t)row0 * ld2 + c2]           = acc[mi][nj][0];
                    C2[(size_t)row0 * ld2 + c2 + 1]       = acc[mi][nj][1];
                    C2[(size_t)(row0 + 8) * ld2 + c2]     = acc[mi][nj][2];
                    C2[(size_t)(row0 + 8) * ld2 + c2 + 1] = acc[mi][nj][3];
                }
            }
        }
    }
}

// ---------------- merge two K-split slabs into split C ----------------
__global__ void ksum2(const float* __restrict__ p, float* __restrict__ C1, int ld1,
                      float* __restrict__ C2, int ld2, int n1, int M, int N) {
    int i = (blockIdx.x * blockDim.x + threadIdx.x) * 4;
    if (i >= M * N) return;
    const float* p1 = p + (size_t)M * N;
    float4 a = *(const float4*)(p + i);
    float4 b = *(const float4*)(p1 + i);
    float4 v = make_float4(a.x + b.x, a.y + b.y, a.z + b.z, a.w + b.w);
    const int row = i / N, col = i % N;
    if (col < n1) *(float4*)(C1 + (size_t)row * ld1 + col) = v;
    else          *(float4*)(C2 + (size_t)row * ld2 + col - n1) = v;
}

// ---------------- RMSNorm ----------------
__global__ void rmsnorm_kernel(const float* __restrict__ in, const float* __restrict__ w,
                               float* __restrict__ out, int n, int in_stride, int out_stride) {
    const int row = blockIdx.x;
    const float* p = in + (size_t)row * in_stride;
    float ss = 0.f;
    for (int i = threadIdx.x; i < n; i += blockDim.x) {
        float v = p[i];
        ss += v * v;
    }
    __shared__ float red[8];
#pragma unroll
    for (int o = 16; o > 0; o >>= 1) ss += __shfl_xor_sync(0xffffffff, ss, o);
    if ((threadIdx.x & 31) == 0) red[threadIdx.x >> 5] = ss;
    __syncthreads();
    if (threadIdx.x < 8) {
        float v = red[threadIdx.x];
#pragma unroll
        for (int o = 4; o > 0; o >>= 1) v += __shfl_xor_sync(0xff, v, o);
        if (threadIdx.x == 0) red[0] = v;
    }
    __syncthreads();
    const float scale = rsqrtf(red[0] / (float)n + EPS);
    float* q = out + (size_t)row * out_stride;
    for (int i = threadIdx.x; i < n; i += blockDim.x) q[i] = p[i] * scale * w[i];
}

// ---------------- RoPE + pack Q/K bf16 hi/lo [h][s][d] ----------------
__global__ void rope_pack_bf16(const float* __restrict__ q, const float* __restrict__ kv,
                               const float* __restrict__ kvup,
                               const float* __restrict__ cosT, const float* __restrict__ sinT,
                               __nv_bfloat16* __restrict__ qh, __nv_bfloat16* __restrict__ ql,
                               __nv_bfloat16* __restrict__ kh, __nv_bfloat16* __restrict__ kl) {
    const int s = blockIdx.x;
    const int h = blockIdx.y;
    const int d = threadIdx.x;

    float qv, kvv;
    if (d < ROPE) {
        const float c = cosT[s * ROPE + d];
        const float sn = sinT[s * ROPE + d];
        const int dro = (d < 32) ? d + 32 : d - 32;
        const float sgn = (d < 32) ? -1.f : 1.f;
        const float xq = q[(size_t)s * (NH * QDIM) + h * QDIM + d];
        const float xqo = q[(size_t)s * (NH * QDIM) + h * QDIM + dro];
        qv = xq * c + sgn * xqo * sn;
        const float xk = kv[(size_t)s * (KVR + ROPE) + KVR + d];
        const float xko = kv[(size_t)s * (KVR + ROPE) + KVR + dro];
        kvv = xk * c + sgn * xko * sn;
    } else {
        qv = q[(size_t)s * (NH * QDIM) + h * QDIM + d];
        kvv = kvup[(size_t)s * (NH * 2 * HD) + h * (2 * HD) + (d - ROPE)];
    }
    qv *= SCALE_F;
    const size_t o = ((size_t)h * S_LEN + s) * QDIM + d;
    __nv_bfloat16 hq = __float2bfloat16(qv);
    qh[o] = hq;
    ql[o] = __float2bfloat16(qv - __bfloat162float(hq));
    __nv_bfloat16 hk = __float2bfloat16(kvv);
    kh[o] = hk;
    kl[o] = __float2bfloat16(kvv - __bfloat162float(hk));
}

// ---------------- V transpose-pack ----------------
__global__ void v_pack(const float* __restrict__ kvup,
                       __nv_bfloat16* __restrict__ vh, __nv_bfloat16* __restrict__ vl) {
    __shared__ float tile[32][33];
    const int s0 = blockIdx.x * 32, d0 = blockIdx.y * 32, h = blockIdx.z;
    const int tx = threadIdx.x, ty = threadIdx.y;
#pragma unroll
    for (int i = 0; i < 4; i++) {
        const int s = s0 + ty + i * 8;
        tile[ty + i * 8][tx] = kvup[(size_t)s * (NH * 2 * HD) + h * (2 * HD) + HD + d0 + tx];
    }
    __syncthreads();
#pragma unroll
    for (int i = 0; i < 4; i++) {
        const int dv = d0 + ty + i * 8;
        const float v = tile[tx][ty + i * 8];
        __nv_bfloat16 hv = __float2bfloat16(v);
        const size_t o = ((size_t)(h * HD + dv)) * S_LEN + s0 + tx;
        vh[o] = hv;
        vl[o] = __float2bfloat16(v - __bfloat162float(hv));
    }
}

// ---------------- tensor-core flash attention (validated R5/R8) ----------------
#define QSTR 200
#define VSTR 72
#define ATTN_SMEM ((128 * QSTR * 2 + 64 * QSTR * 2 + 128 * VSTR * 2) * 2)

__device__ __forceinline__ uint32_t pack_bf2(float a, float b) {
    __nv_bfloat162 t = __floats2bfloat162_rn(a, b);
    return *(uint32_t*)&t;
}

__global__ void __launch_bounds__(256) attn_mma(
    const __nv_bfloat16* __restrict__ qh, const __nv_bfloat16* __restrict__ ql,
    const __nv_bfloat16* __restrict__ kh, const __nv_bfloat16* __restrict__ kl,
    const __nv_bfloat16* __restrict__ vh, const __nv_bfloat16* __restrict__ vl,
    float* __restrict__ outp) {
    extern __shared__ __nv_bfloat16 sm[];
    __nv_bfloat16* sQh = sm;
    __nv_bfloat16* sQl = sQh + 128 * QSTR;
    __nv_bfloat16* sKh = sQl + 128 * QSTR;
    __nv_bfloat16* sKl = sKh + 64 * QSTR;
    __nv_bfloat16* sVh = sKl + 64 * QSTR;
    __nv_bfloat16* sVl = sVh + 128 * VSTR;

    const int qb = (gridDim.x - 1 - blockIdx.x) * 128;
    const int h = blockIdx.y;
    const int tid = threadIdx.x;
    const int wid = tid >> 5, lane = tid & 31;

    const __nv_bfloat16* qhb = qh + ((size_t)h * S_LEN + qb) * QDIM;
    const __nv_bfloat16* qlb = ql + ((size_t)h * S_LEN + qb) * QDIM;
    for (int i = tid; i < 128 * 24; i += 256) {
        const int r = i / 24, c = (i % 24) * 8;
        *(uint4*)&sQh[r * QSTR + c] = *(const uint4*)&qhb[(size_t)r * QDIM + c];
        *(uint4*)&sQl[r * QSTR + c] = *(const uint4*)&qlb[(size_t)r * QDIM + c];
    }

    float o_r[16][4];
#pragma unroll
    for (int n = 0; n < 16; n++)
#pragma unroll
        for (int r = 0; r < 4; r++) o_r[n][r] = 0.f;
    float m0 = -1e30f, m1 = -1e30f, l0 = 0.f, l1 = 0.f;

    const int r0w = qb + wid * 16 + (lane >> 2);
    const int r1w = r0w + 8;

    const __nv_bfloat16* khb = kh + (size_t)h * S_LEN * QDIM;
    const __nv_bfloat16* klb = kl + (size_t)h * S_LEN * QDIM;
    const __nv_bfloat16* vhb = vh + (size_t)h * HD * S_LEN;
    const __nv_bfloat16* vlb = vl + (size_t)h * HD * S_LEN;

    const int ntiles = qb / 64 + 2;
    for (int t = 0; t < ntiles; t++) {
        const int kb = t * 64;
        __syncthreads();
        for (int i = tid; i < 64 * 24; i += 256) {
            const int r = i / 24, c = (i % 24) * 8;
            *(uint4*)&sKh[r * QSTR + c] = *(const uint4*)&khb[(size_t)(kb + r) * QDIM + c];
            *(uint4*)&sKl[r * QSTR + c] = *(const uint4*)&klb[(size_t)(kb + r) * QDIM + c];
        }
        for (int i = tid; i < 128 * 8; i += 256) {
            const int r = i / 8, c = (i % 8) * 8;
            *(uint4*)&sVh[r * VSTR + c] = *(const uint4*)&vhb[(size_t)r * S_LEN + kb + c];
            *(uint4*)&sVl[r * VSTR + c] = *(const uint4*)&vlb[(size_t)r * S_LEN + kb + c];
        }
        __syncthreads();

        if (kb > qb + wid * 16 + 15) continue;

        float sc[8][4];
#pragma unroll
        for (int j = 0; j < 8; j++)
#pragma unroll
            for (int r = 0; r < 4; r++) sc[j][r] = 0.f;

        const int arow = wid * 16 + (lane & 15);
        const int xcol = (lane >> 4) * 8;
#pragma unroll
        for (int ks = 0; ks < 12; ks++) {
            uint32_t aH[4], aL[4];
            LDMX4(aH, &sQh[arow * QSTR + ks * 16 + xcol]);
            LDMX4(aL, &sQl[arow * QSTR + ks * 16 + xcol]);
#pragma unroll
            for (int g = 0; g < 4; g++) {
                uint32_t rh[4], rl[4];
                LDMX4(rh, &sKh[(g * 16 + (lane & 15)) * QSTR + ks * 16 + xcol]);
                LDMX4(rl, &sKl[(g * 16 + (lane & 15)) * QSTR + ks * 16 + xcol]);
                uint32_t bh0[2] = {rh[0], rh[2]}, bh1[2] = {rh[1], rh[3]};
                uint32_t bl0[2] = {rl[0], rl[2]}, bl1[2] = {rl[1], rl[3]};
                MMA_BF16(sc[2 * g],     aH, bh0);
                MMA_BF16(sc[2 * g],     aH, bl0);
                MMA_BF16(sc[2 * g],     aL, bh0);
                MMA_BF16(sc[2 * g + 1], aH, bh1);
                MMA_BF16(sc[2 * g + 1], aH, bl1);
                MMA_BF16(sc[2 * g + 1], aL, bh1);
            }
        }

        if (kb + 63 > r0w) {
#pragma unroll
            for (int j = 0; j < 8; j++) {
                const int colg = kb + j * 8 + (lane & 3) * 2;
                if (colg     > r0w) sc[j][0] = -1e30f;
                if (colg + 1 > r0w) sc[j][1] = -1e30f;
                if (colg     > r1w) sc[j][2] = -1e30f;
                if (colg + 1 > r1w) sc[j][3] = -1e30f;
            }
        }

        float mx0 = -1e30f, mx1 = -1e30f;
#pragma unroll
        for (int j = 0; j < 8; j++) {
            mx0 = fmaxf(mx0, fmaxf(sc[j][0], sc[j][1]));
            mx1 = fmaxf(mx1, fmaxf(sc[j][2], sc[j][3]));
        }
        mx0 = fmaxf(mx0, __shfl_xor_sync(0xffffffff, mx0, 1));
        mx0 = fmaxf(mx0, __shfl_xor_sync(0xffffffff, mx0, 2));
        mx1 = fmaxf(mx1, __shfl_xor_sync(0xffffffff, mx1, 1));
        mx1 = fmaxf(mx1, __shfl_xor_sync(0xffffffff, mx1, 2));
        const float mn0 = fmaxf(m0, mx0), mn1 = fmaxf(m1, mx1);
        const float al0 = __expf(m0 - mn0), al1 = __expf(m1 - mn1);
        float rs0 = 0.f, rs1 = 0.f;
#pragma unroll
        for (int j = 0; j < 8; j++) {
            sc[j][0] = __expf(sc[j][0] - mn0);
            sc[j][1] = __expf(sc[j][1] - mn0);
            sc[j][2] = __expf(sc[j][2] - mn1);
            sc[j][3] = __expf(sc[j][3] - mn1);
            rs0 += sc[j][0] + sc[j][1];
            rs1 += sc[j][2] + sc[j][3];
        }
        rs0 += __shfl_xor_sync(0xffffffff, rs0, 1);
        rs0 += __shfl_xor_sync(0xffffffff, rs0, 2);
        rs1 += __shfl_xor_sync(0xffffffff, rs1, 1);
        rs1 += __shfl_xor_sync(0xffffffff, rs1, 2);
        l0 = l0 * al0 + rs0;
        l1 = l1 * al1 + rs1;
        m0 = mn0;
        m1 = mn1;
#pragma unroll
        for (int n = 0; n < 16; n++) {
            o_r[n][0] *= al0; o_r[n][1] *= al0;
            o_r[n][2] *= al1; o_r[n][3] *= al1;
        }

#pragma unroll
        for (int ku = 0; ku < 4; ku++) {
            float ph[8], pl[8];
#pragma unroll
            for (int e = 0; e < 4; e++) {
                const float v0 = sc[2 * ku][e], v1 = sc[2 * ku + 1][e];
                const float h0 = __bfloat162float(__float2bfloat16(v0));
                const float h1 = __bfloat162float(__float2bfloat16(v1));
                ph[e] = h0;     pl[e] = v0 - h0;
                ph[4 + e] = h1; pl[4 + e] = v1 - h1;
            }
            uint32_t aPh[4], aPl[4];
            aPh[0] = pack_bf2(ph[0], ph[1]);  aPl[0] = pack_bf2(pl[0], pl[1]);
            aPh[1] = pack_bf2(ph[2], ph[3]);  aPl[1] = pack_bf2(pl[2], pl[3]);
            aPh[2] = pack_bf2(ph[4], ph[5]);  aPl[2] = pack_bf2(pl[4], pl[5]);
            aPh[3] = pack_bf2(ph[6], ph[7]);  aPl[3] = pack_bf2(pl[6], pl[7]);
            const int vc = ku * 16 + xcol;
#pragma unroll
            for (int g = 0; g < 8; g++) {
                uint32_t rh[4], rl[4];
                LDMX4(rh, &sVh[(g * 16 + (lane & 15)) * VSTR + vc]);
                LDMX4(rl, &sVl[(g * 16 + (lane & 15)) * VSTR + vc]);
                uint32_t bh0[2] = {rh[0], rh[2]}, bh1[2] = {rh[1], rh[3]};
                uint32_t bl0[2] = {rl[0], rl[2]}, bl1[2] = {rl[1], rl[3]};
                MMA_BF16(o_r[2 * g],     aPh, bh0);
                MMA_BF16(o_r[2 * g],     aPh, bl0);
                MMA_BF16(o_r[2 * g],     aPl, bh0);
                MMA_BF16(o_r[2 * g + 1], aPh, bh1);
                MMA_BF16(o_r[2 * g + 1], aPh, bl1);
                MMA_BF16(o_r[2 * g + 1], aPl, bh1);
            }
        }
    }

    const float inv0 = 1.f / l0, inv1 = 1.f / l1;
#pragma unroll
    for (int n = 0; n < 16; n++) {
        const int col = h * HD + n * 8 + (lane & 3) * 2;
        outp[(size_t)r0w * (NH * HD) + col]     = o_r[n][0] * inv0;
        outp[(size_t)r0w * (NH * HD) + col + 1] = o_r[n][1] * inv0;
        outp[(size_t)r1w * (NH * HD) + col]     = o_r[n][2] * inv1;
        outp[(size_t)r1w * (NH * HD) + col + 1] = o_r[n][3] * inv1;
    }
}

// ---------------- launch ----------------
static inline void split_launch(const float* in, __nv_bfloat16* hi, __nv_bfloat16* lo, int n) {
    split_kernel<<<(n / 4 + 255) / 256, 256>>>(in, hi, lo, n);
}

extern "C" void kernel_launch(void* const* d_in, const int* in_sizes, int n_in,
                              void* d_out, int out_size) {
    const float* x          = (const float*)d_in[0];
    const float* cosp       = (const float*)d_in[1];
    const float* sinp       = (const float*)d_in[2];
    const float* q_a_w      = (const float*)d_in[3];
    const float* q_a_norm_w = (const float*)d_in[4];
    const float* q_b_w      = (const float*)d_in[5];
    const float* kv_a_w     = (const float*)d_in[6];
    const float* kv_a_norm_w= (const float*)d_in[7];
    const float* kv_b_w     = (const float*)d_in[8];
    const float* o_w        = (const float*)d_in[9];

    float *qlat, *q, *kv, *kvn, *kvup, *attn, *part;
    __nv_bfloat16 *xh, *xl, *ah, *al, *wh, *wl;
    __nv_bfloat16 *qbh, *qbl, *kbh, *kbl, *vbh, *vbl;
    cudaGetSymbolAddress((void**)&qlat, g_qlat);
    cudaGetSymbolAddress((void**)&q,    g_q);
    cudaGetSymbolAddress((void**)&kv,   g_kv);
    cudaGetSymbolAddress((void**)&kvn,  g_kvn);
    cudaGetSymbolAddress((void**)&kvup, g_kvup);
    cudaGetSymbolAddress((void**)&attn, g_attn);
    cudaGetSymbolAddress((void**)&part, g_part);
    cudaGetSymbolAddress((void**)&xh,   g_xh);
    cudaGetSymbolAddress((void**)&xl,   g_xl);
    cudaGetSymbolAddress((void**)&ah,   g_ah);
    cudaGetSymbolAddress((void**)&al,   g_al);
    cudaGetSymbolAddress((void**)&wh,   g_wh);
    cudaGetSymbolAddress((void**)&wl,   g_wl);
    cudaGetSymbolAddress((void**)&qbh,  g_qbh);
    cudaGetSymbolAddress((void**)&qbl,  g_qbl);
    cudaGetSymbolAddress((void**)&kbh,  g_kbh);
    cudaGetSymbolAddress((void**)&kbl,  g_kbl);
    cudaGetSymbolAddress((void**)&vbh,  g_vbh);
    cudaGetSymbolAddress((void**)&vbl,  g_vbl);

    cudaFuncSetAttribute(gemm_bf16x3, cudaFuncAttributeMaxDynamicSharedMemorySize, GEMM_SMEM);
    cudaFuncSetAttribute(attn_mma, cudaFuncAttributeMaxDynamicSharedMemorySize, ATTN_SMEM);

    split_launch(x, xh, xl, S_LEN * HID);

    // 1+4 fused, K-split 2) [qlat | kv] = x @ [q_a_w ; kv_a_w]^T  (N = 2496)
    split_launch(q_a_w, wh, wl, QR * HID);
    split_launch(kv_a_w, wh + (size_t)QR * HID, wl + (size_t)QR * HID, (KVR + ROPE) * HID);
    {
        const int N = QR + KVR + ROPE;
        gemm_bf16x3<<<dim3((N + 127) / 128, S_LEN / 128, 2), 256, GEMM_SMEM>>>(
            xh, xl, wh, wl, nullptr, 0, nullptr, 0, 0, part, S_LEN, N, HID);
        ksum2<<<(S_LEN * N / 4 + 255) / 256, 256>>>(part, qlat, QR, kv, KVR + ROPE, QR, S_LEN, N);
    }
    // 2) rmsnorm q_lat
    rmsnorm_kernel<<<S_LEN, 256>>>(qlat, q_a_norm_w, qlat, QR, QR, QR);
    // 5) rmsnorm kv -> kvn
    rmsnorm_kernel<<<S_LEN, 256>>>(kv, kv_a_norm_w, kvn, KVR, KVR + ROPE, KVR);
    // 3) q = q_lat @ q_b_w^T (direct write)
    split_launch(qlat, ah, al, S_LEN * QR);
    split_launch(q_b_w, wh, wl, NH * QDIM * QR);
    gemm_bf16x3<<<dim3((NH * QDIM) / 128, S_LEN / 128, 1), 256, GEMM_SMEM>>>(
        ah, al, wh, wl, q, NH * QDIM, q, NH * QDIM, NH * QDIM, nullptr, S_LEN, NH * QDIM, QR);
    // 6) kv_up = kvn @ kv_b_w^T (direct write)
    split_launch(kvn, ah, al, S_LEN * KVR);
    split_launch(kv_b_w, wh, wl, NH * 2 * HD * KVR);
    gemm_bf16x3<<<dim3((NH * 2 * HD) / 128, S_LEN / 128, 1), 256, GEMM_SMEM>>>(
        ah, al, wh, wl, kvup, NH * 2 * HD, kvup, NH * 2 * HD, NH * 2 * HD, nullptr,
        S_LEN, NH * 2 * HD, KVR);
    // 7) rope + packs
    rope_pack_bf16<<<dim3(S_LEN, NH), QDIM>>>(q, kv, kvup, cosp, sinp, qbh, qbl, kbh, kbl);
    v_pack<<<dim3(S_LEN / 32, HD / 32, NH), dim3(32, 8)>>>(kvup, vbh, vbl);
    // 8) attention
    attn_mma<<<dim3(S_LEN / 128, NH), 256, ATTN_SMEM>>>(qbh, qbl, kbh, kbl, vbh, vbl, attn);
    // 9) out = attn @ o_w^T (direct write, no K-split)
    split_launch(attn, ah, al, S_LEN * NH * HD);
    split_launch(o_w, wh, wl, HID * NH * HD);
    gemm_bf16x3<<<dim3(HID / 128, S_LEN / 128, 1), 256, GEMM_SMEM>>>(
        ah, al, wh, wl, (float*)d_out, HID, (float*)d_out, HID, HID, nullptr,
        S_LEN, HID, HID);
}

// round 16
// speedup vs baseline: 1.1525x; 1.0134x over previous
#include <cuda_runtime.h>
#include <cuda_bf16.h>
#include <cstdint>

#define S_LEN 2048
#define HID   4096
#define NH    32
#define HD    128
#define ROPE  64
#define QR    1536
#define KVR   896
#define QDIM  192
#define EPS   1e-6f
#define SCALE_F 0.07216878364870322f  // 1/sqrt(192)
#define NFUSE (QR + KVR + ROPE)       // 2496

// ---------------- scratch ----------------
__device__ float g_qlat[S_LEN * QR];
__device__ float g_q[S_LEN * NH * QDIM];
__device__ float g_kv[S_LEN * (KVR + ROPE)];
__device__ float g_kvn[S_LEN * KVR];
__device__ float g_kvup[S_LEN * NH * 2 * HD];
__device__ float g_attn[S_LEN * NH * HD];
__device__ float g_part[4 * (size_t)S_LEN * NFUSE];   // 4 K-split slabs (82 MB)

__device__ __nv_bfloat16 g_xh[S_LEN * HID];
__device__ __nv_bfloat16 g_xl[S_LEN * HID];
__device__ __nv_bfloat16 g_ah[S_LEN * HID];
__device__ __nv_bfloat16 g_al[S_LEN * HID];
__device__ __nv_bfloat16 g_wh[HID * HID];
__device__ __nv_bfloat16 g_wl[HID * HID];

__device__ __nv_bfloat16 g_qbh[(size_t)NH * S_LEN * QDIM];
__device__ __nv_bfloat16 g_qbl[(size_t)NH * S_LEN * QDIM];
__device__ __nv_bfloat16 g_kbh[(size_t)NH * S_LEN * QDIM];
__device__ __nv_bfloat16 g_kbl[(size_t)NH * S_LEN * QDIM];
__device__ __nv_bfloat16 g_vbh[(size_t)NH * HD * S_LEN];
__device__ __nv_bfloat16 g_vbl[(size_t)NH * HD * S_LEN];

// ---------------- helpers ----------------
#define MMA_BF16(c, a, b)                                                            \
    asm volatile(                                                                    \
        "mma.sync.aligned.m16n8k16.row.col.f32.bf16.bf16.f32 "                       \
        "{%0,%1,%2,%3}, {%4,%5,%6,%7}, {%8,%9}, {%0,%1,%2,%3};"                      \
        : "+f"(c[0]), "+f"(c[1]), "+f"(c[2]), "+f"(c[3])                             \
        : "r"(a[0]), "r"(a[1]), "r"(a[2]), "r"(a[3]), "r"(b[0]), "r"(b[1]))

#define LDMX4(r, p)                                                                  \
    asm volatile("ldmatrix.sync.aligned.m8n8.x4.shared.b16 {%0,%1,%2,%3}, [%4];"     \
                 : "=r"(r[0]), "=r"(r[1]), "=r"(r[2]), "=r"(r[3])                    \
                 : "r"((uint32_t)__cvta_generic_to_shared(p)))

#define LDMX2(r, p)                                                                  \
    asm volatile("ldmatrix.sync.aligned.m8n8.x2.shared.b16 {%0,%1}, [%2];"           \
                 : "=r"(r[0]), "=r"(r[1])                                            \
                 : "r"((uint32_t)__cvta_generic_to_shared(p)))

__device__ __forceinline__ void cp16(void* dst_smem, const void* src) {
    uint32_t d = (uint32_t)__cvta_generic_to_shared(dst_smem);
    asm volatile("cp.async.cg.shared.global [%0], [%1], 16;" :: "r"(d), "l"(src));
}
#define CP_COMMIT() asm volatile("cp.async.commit_group;" ::: "memory")
#define CP_WAIT(n)  asm volatile("cp.async.wait_group %0;" :: "n"(n) : "memory")

// ---------------- fp32 -> (bf16 hi, bf16 lo) split ----------------
__global__ void split_kernel(const float* __restrict__ in, __nv_bfloat16* __restrict__ hi,
                             __nv_bfloat16* __restrict__ lo, int n) {
    int i = (blockIdx.x * blockDim.x + threadIdx.x) * 4;
    if (i >= n) return;
    float4 v = *(const float4*)(in + i);
    float vv[4] = {v.x, v.y, v.z, v.w};
    __nv_bfloat16 h[4], l[4];
#pragma unroll
    for (int j = 0; j < 4; j++) {
        h[j] = __float2bfloat16(vv[j]);
        l[j] = __float2bfloat16(vv[j] - __bfloat162float(h[j]));
    }
    __nv_bfloat162* hp = (__nv_bfloat162*)(hi + i);
    __nv_bfloat162* lp = (__nv_bfloat162*)(lo + i);
    hp[0] = __halves2bfloat162(h[0], h[1]);
    hp[1] = __halves2bfloat162(h[2], h[3]);
    lp[0] = __halves2bfloat162(l[0], l[1]);
    lp[1] = __halves2bfloat162(l[2], l[3]);
}

// ---------------- split-bf16 GEMM (R8 exact core) + optional K-split ----------------
#define LDSB 40
#define ST_TILE (128 * LDSB)
#define GEMM_SMEM (2 * 4 * ST_TILE * 2)   // 80 KB -> 2 CTAs/SM

__global__ void __launch_bounds__(256, 2) gemm_bf16x3(
    const __nv_bfloat16* __restrict__ Ah, const __nv_bfloat16* __restrict__ Al,
    const __nv_bfloat16* __restrict__ Bh, const __nv_bfloat16* __restrict__ Bl,
    float* __restrict__ C1, int ld1, float* __restrict__ C2, int ld2, int n1,
    float* __restrict__ Cp, int M, int N, int K) {
    extern __shared__ __nv_bfloat16 smx[];
    const int tid = threadIdx.x;
    const int wid = tid >> 5, lane = tid & 31;
    const int bm = blockIdx.y * 128;
    const int bn = blockIdx.x * 128;
    const int wm = (wid >> 2) * 64;
    const int wn = (wid & 3) * 32;

    const int Ksub = K / gridDim.z;
    const int Koff = blockIdx.z * Ksub;

    const int lr = tid >> 1;
    const int lk = (tid & 1) * 16;
    const __nv_bfloat16* gAh = Ah + (size_t)(bm + lr) * K + Koff + lk;
    const __nv_bfloat16* gAl = Al + (size_t)(bm + lr) * K + Koff + lk;
    const int brow = min(bn + lr, N - 1);
    const __nv_bfloat16* gBh = Bh + (size_t)brow * K + Koff + lk;
    const __nv_bfloat16* gBl = Bl + (size_t)brow * K + Koff + lk;

    const int NS = Ksub / 32;
    const int soff = lr * LDSB + lk;

    auto load_stage = [&](int s) {
        __nv_bfloat16* buf = smx + (s & 1) * 4 * ST_TILE;
        const int k0 = s * 32;
        cp16(buf + soff,                    gAh + k0);
        cp16(buf + soff + 8,                gAh + k0 + 8);
        cp16(buf + ST_TILE + soff,          gAl + k0);
        cp16(buf + ST_TILE + soff + 8,      gAl + k0 + 8);
        cp16(buf + 2 * ST_TILE + soff,      gBh + k0);
        cp16(buf + 2 * ST_TILE + soff + 8,  gBh + k0 + 8);
        cp16(buf + 3 * ST_TILE + soff,      gBl + k0);
        cp16(buf + 3 * ST_TILE + soff + 8,  gBl + k0 + 8);
        CP_COMMIT();
    };

    float acc[4][4][4];
#pragma unroll
    for (int i = 0; i < 4; i++)
#pragma unroll
        for (int j = 0; j < 4; j++)
#pragma unroll
            for (int r = 0; r < 4; r++) acc[i][j][r] = 0.f;

    load_stage(0);
    CP_WAIT(0);
    __syncthreads();

    const int ar = wm + (lane & 15);
    const int ac = (lane >> 4) * 8;
    const int br = wn + (lane & 7);
    const int bc = ((lane >> 3) & 1) * 8;

    for (int s = 0; s < NS; s++) {
        if (s + 1 < NS) load_stage(s + 1);

        const __nv_bfloat16* buf = smx + (s & 1) * 4 * ST_TILE;
        const __nv_bfloat16* bAh = buf;
        const __nv_bfloat16* bAl = buf + ST_TILE;
        const __nv_bfloat16* bBh = buf + 2 * ST_TILE;
        const __nv_bfloat16* bBl = buf + 3 * ST_TILE;

#pragma unroll
        for (int kk = 0; kk < 32; kk += 16) {
            uint32_t a_h[4][4], a_l[4][4], b_h[4][2], b_l[4][2];
#pragma unroll
            for (int mi = 0; mi < 4; mi++) {
                LDMX4(a_h[mi], &bAh[(ar + mi * 16) * LDSB + kk + ac]);
                LDMX4(a_l[mi], &bAl[(ar + mi * 16) * LDSB + kk + ac]);
            }
#pragma unroll
            for (int nj = 0; nj < 4; nj++) {
                LDMX2(b_h[nj], &bBh[(br + nj * 8) * LDSB + kk + bc]);
                LDMX2(b_l[nj], &bBl[(br + nj * 8) * LDSB + kk + bc]);
            }
#pragma unroll
            for (int mi = 0; mi < 4; mi++)
#pragma unroll
                for (int nj = 0; nj < 4; nj++) MMA_BF16(acc[mi][nj], a_h[mi], b_h[nj]);
#pragma unroll
            for (int mi = 0; mi < 4; mi++)
#pragma unroll
                for (int nj = 0; nj < 4; nj++) MMA_BF16(acc[mi][nj], a_h[mi], b_l[nj]);
#pragma unroll
            for (int mi = 0; mi < 4; mi++)
#pragma unroll
                for (int nj = 0; nj < 4; nj++) MMA_BF16(acc[mi][nj], a_l[mi], b_h[nj]);
        }

        if (s + 1 < NS) {
            CP_WAIT(0);
            __syncthreads();
        }
    }

    if (gridDim.z > 1) {
        float* dst = Cp + (size_t)blockIdx.z * M * N;
#pragma unroll
        for (int mi = 0; mi < 4; mi++) {
#pragma unroll
            for (int nj = 0; nj < 4; nj++) {
                const int row0 = bm + wm + mi * 16 + (lane >> 2);
                const int col = bn + wn + nj * 8 + (lane & 3) * 2;
                if (col < N) {
                    dst[(size_t)row0 * N + col]           = acc[mi][nj][0];
                    dst[(size_t)row0 * N + col + 1]       = acc[mi][nj][1];
                    dst[(size_t)(row0 + 8) * N + col]     = acc[mi][nj][2];
                    dst[(size_t)(row0 + 8) * N + col + 1] = acc[mi][nj][3];
                }
            }
        }
        return;
    }

#pragma unroll
    for (int mi = 0; mi < 4; mi++) {
#pragma unroll
        for (int nj = 0; nj < 4; nj++) {
            const int row0 = bm + wm + mi * 16 + (lane >> 2);
            const int col = bn + wn + nj * 8 + (lane & 3) * 2;
            if (col < N) {
                if (col < n1) {
                    C1[(size_t)row0 * ld1 + col]           = acc[mi][nj][0];
                    C1[(size_t)row0 * ld1 + col + 1]       = acc[mi][nj][1];
                    C1[(size_t)(row0 + 8) * ld1 + col]     = acc[mi][nj][2];
                    C1[(size_t)(row0 + 8) * ld1 + col + 1] = acc[mi][nj][3];
                } else {
                    const int c2 = col - n1;
                    C2[(size_t)row0 * ld2 + c2]           = acc[mi][nj][0];
                    C2[(size_t)row0 * ld2 + c2 + 1]       = acc[mi][nj][1];
                    C2[(size_t)(row0 + 8) * ld2 + c2]     = acc[mi][nj][2];
                    C2[(size_t)(row0 + 8) * ld2 + c2 + 1] = acc[mi][nj][3];
                }
            }
        }
    }
}

// ---------------- merge four K-split slabs into split C ----------------
__global__ void ksum4(const float* __restrict__ p, float* __restrict__ C1, int ld1,
                      float* __restrict__ C2, int ld2, int n1, int M, int N) {
    int i = (blockIdx.x * blockDim.x + threadIdx.x) * 4;
    if (i >= M * N) return;
    const size_t S = (size_t)M * N;
    float4 a = *(const float4*)(p + i);
    float4 b = *(const float4*)(p + S + i);
    float4 c = *(const float4*)(p + 2 * S + i);
    float4 d = *(const float4*)(p + 3 * S + i);
    float4 v = make_float4((a.x + b.x) + (c.x + d.x), (a.y + b.y) + (c.y + d.y),
                           (a.z + b.z) + (c.z + d.z), (a.w + b.w) + (c.w + d.w));
    const int row = i / N, col = i % N;
    if (col < n1) *(float4*)(C1 + (size_t)row * ld1 + col) = v;
    else          *(float4*)(C2 + (size_t)row * ld2 + col - n1) = v;
}

// ---------------- RMSNorm ----------------
__global__ void rmsnorm_kernel(const float* __restrict__ in, const float* __restrict__ w,
                               float* __restrict__ out, int n, int in_stride, int out_stride) {
    const int row = blockIdx.x;
    const float* p = in + (size_t)row * in_stride;
    float ss = 0.f;
    for (int i = threadIdx.x; i < n; i += blockDim.x) {
        float v = p[i];
        ss += v * v;
    }
    __shared__ float red[8];
#pragma unroll
    for (int o = 16; o > 0; o >>= 1) ss += __shfl_xor_sync(0xffffffff, ss, o);
    if ((threadIdx.x & 31) == 0) red[threadIdx.x >> 5] = ss;
    __syncthreads();
    if (threadIdx.x < 8) {
        float v = red[threadIdx.x];
#pragma unroll
        for (int o = 4; o > 0; o >>= 1) v += __shfl_xor_sync(0xff, v, o);
        if (threadIdx.x == 0) red[0] = v;
    }
    __syncthreads();
    const float scale = rsqrtf(red[0] / (float)n + EPS);
    float* q = out + (size_t)row * out_stride;
    for (int i = threadIdx.x; i < n; i += blockDim.x) q[i] = p[i] * scale * w[i];
}

// ---------------- RoPE + pack Q/K bf16 hi/lo [h][s][d] ----------------
__global__ void rope_pack_bf16(const float* __restrict__ q, const float* __restrict__ kv,
                               const float* __restrict__ kvup,
                               const float* __restrict__ cosT, const float* __restrict__ sinT,
                               __nv_bfloat16* __restrict__ qh, __nv_bfloat16* __restrict__ ql,
                               __nv_bfloat16* __restrict__ kh, __nv_bfloat16* __restrict__ kl) {
    const int s = blockIdx.x;
    const int h = blockIdx.y;
    const int d = threadIdx.x;

    float qv, kvv;
    if (d < ROPE) {
        const float c = cosT[s * ROPE + d];
        const float sn = sinT[s * ROPE + d];
        const int dro = (d < 32) ? d + 32 : d - 32;
        const float sgn = (d < 32) ? -1.f : 1.f;
        const float xq = q[(size_t)s * (NH * QDIM) + h * QDIM + d];
        const float xqo = q[(size_t)s * (NH * QDIM) + h * QDIM + dro];
        qv = xq * c + sgn * xqo * sn;
        const float xk = kv[(size_t)s * (KVR + ROPE) + KVR + d];
        const float xko = kv[(size_t)s * (KVR + ROPE) + KVR + dro];
        kvv = xk * c + sgn * xko * sn;
    } else {
        qv = q[(size_t)s * (NH * QDIM) + h * QDIM + d];
        kvv = kvup[(size_t)s * (NH * 2 * HD) + h * (2 * HD) + (d - ROPE)];
    }
    qv *= SCALE_F;
    const size_t o = ((size_t)h * S_LEN + s) * QDIM + d;
    __nv_bfloat16 hq = __float2bfloat16(qv);
    qh[o] = hq;
    ql[o] = __float2bfloat16(qv - __bfloat162float(hq));
    __nv_bfloat16 hk = __float2bfloat16(kvv);
    kh[o] = hk;
    kl[o] = __float2bfloat16(kvv - __bfloat162float(hk));
}

// ---------------- V transpose-pack ----------------
__global__ void v_pack(const float* __restrict__ kvup,
                       __nv_bfloat16* __restrict__ vh, __nv_bfloat16* __restrict__ vl) {
    __shared__ float tile[32][33];
    const int s0 = blockIdx.x * 32, d0 = blockIdx.y * 32, h = blockIdx.z;
    const int tx = threadIdx.x, ty = threadIdx.y;
#pragma unroll
    for (int i = 0; i < 4; i++) {
        const int s = s0 + ty + i * 8;
        tile[ty + i * 8][tx] = kvup[(size_t)s * (NH * 2 * HD) + h * (2 * HD) + HD + d0 + tx];
    }
    __syncthreads();
#pragma unroll
    for (int i = 0; i < 4; i++) {
        const int dv = d0 + ty + i * 8;
        const float v = tile[tx][ty + i * 8];
        __nv_bfloat16 hv = __float2bfloat16(v);
        const size_t o = ((size_t)(h * HD + dv)) * S_LEN + s0 + tx;
        vh[o] = hv;
        vl[o] = __float2bfloat16(v - __bfloat162float(hv));
    }
}

// ---------------- tensor-core flash attention (validated R5/R8) ----------------
#define QSTR 200
#define VSTR 72
#define ATTN_SMEM ((128 * QSTR * 2 + 64 * QSTR * 2 + 128 * VSTR * 2) * 2)

__device__ __forceinline__ uint32_t pack_bf2(float a, float b) {
    __nv_bfloat162 t = __floats2bfloat162_rn(a, b);
    return *(uint32_t*)&t;
}

__global__ void __launch_bounds__(256) attn_mma(
    const __nv_bfloat16* __restrict__ qh, const __nv_bfloat16* __restrict__ ql,
    const __nv_bfloat16* __restrict__ kh, const __nv_bfloat16* __restrict__ kl,
    const __nv_bfloat16* __restrict__ vh, const __nv_bfloat16* __restrict__ vl,
    float* __restrict__ outp) {
    extern __shared__ __nv_bfloat16 sm[];
    __nv_bfloat16* sQh = sm;
    __nv_bfloat16* sQl = sQh + 128 * QSTR;
    __nv_bfloat16* sKh = sQl + 128 * QSTR;
    __nv_bfloat16* sKl = sKh + 64 * QSTR;
    __nv_bfloat16* sVh = sKl + 64 * QSTR;
    __nv_bfloat16* sVl = sVh + 128 * VSTR;

    const int qb = (gridDim.x - 1 - blockIdx.x) * 128;
    const int h = blockIdx.y;
    const int tid = threadIdx.x;
    const int wid = tid >> 5, lane = tid & 31;

    const __nv_bfloat16* qhb = qh + ((size_t)h * S_LEN + qb) * QDIM;
    const __nv_bfloat16* qlb = ql + ((size_t)h * S_LEN + qb) * QDIM;
    for (int i = tid; i < 128 * 24; i += 256) {
        const int r = i / 24, c = (i % 24) * 8;
        *(uint4*)&sQh[r * QSTR + c] = *(const uint4*)&qhb[(size_t)r * QDIM + c];
        *(uint4*)&sQl[r * QSTR + c] = *(const uint4*)&qlb[(size_t)r * QDIM + c];
    }

    float o_r[16][4];
#pragma unroll
    for (int n = 0; n < 16; n++)
#pragma unroll
        for (int r = 0; r < 4; r++) o_r[n][r] = 0.f;
    float m0 = -1e30f, m1 = -1e30f, l0 = 0.f, l1 = 0.f;

    const int r0w = qb + wid * 16 + (lane >> 2);
    const int r1w = r0w + 8;

    const __nv_bfloat16* khb = kh + (size_t)h * S_LEN * QDIM;
    const __nv_bfloat16* klb = kl + (size_t)h * S_LEN * QDIM;
    const __nv_bfloat16* vhb = vh + (size_t)h * HD * S_LEN;
    const __nv_bfloat16* vlb = vl + (size_t)h * HD * S_LEN;

    const int ntiles = qb / 64 + 2;
    for (int t = 0; t < ntiles; t++) {
        const int kb = t * 64;
        __syncthreads();
        for (int i = tid; i < 64 * 24; i += 256) {
            const int r = i / 24, c = (i % 24) * 8;
            *(uint4*)&sKh[r * QSTR + c] = *(const uint4*)&khb[(size_t)(kb + r) * QDIM + c];
            *(uint4*)&sKl[r * QSTR + c] = *(const uint4*)&klb[(size_t)(kb + r) * QDIM + c];
        }
        for (int i = tid; i < 128 * 8; i += 256) {
            const int r = i / 8, c = (i % 8) * 8;
            *(uint4*)&sVh[r * VSTR + c] = *(const uint4*)&vhb[(size_t)r * S_LEN + kb + c];
            *(uint4*)&sVl[r * VSTR + c] = *(const uint4*)&vlb[(size_t)r * S_LEN + kb + c];
        }
        __syncthreads();

        if (kb > qb + wid * 16 + 15) continue;

        float sc[8][4];
#pragma unroll
        for (int j = 0; j < 8; j++)
#pragma unroll
            for (int r = 0; r < 4; r++) sc[j][r] = 0.f;

        const int arow = wid * 16 + (lane & 15);
        const int xcol = (lane >> 4) * 8;
#pragma unroll
        for (int ks = 0; ks < 12; ks++) {
            uint32_t aH[4], aL[4];
            LDMX4(aH, &sQh[arow * QSTR + ks * 16 + xcol]);
            LDMX4(aL, &sQl[arow * QSTR + ks * 16 + xcol]);
#pragma unroll
            for (int g = 0; g < 4; g++) {
                uint32_t rh[4], rl[4];
                LDMX4(rh, &sKh[(g * 16 + (lane & 15)) * QSTR + ks * 16 + xcol]);
                LDMX4(rl, &sKl[(g * 16 + (lane & 15)) * QSTR + ks * 16 + xcol]);
                uint32_t bh0[2] = {rh[0], rh[2]}, bh1[2] = {rh[1], rh[3]};
                uint32_t bl0[2] = {rl[0], rl[2]}, bl1[2] = {rl[1], rl[3]};
                MMA_BF16(sc[2 * g],     aH, bh0);
                MMA_BF16(sc[2 * g],     aH, bl0);
                MMA_BF16(sc[2 * g],     aL, bh0);
                MMA_BF16(sc[2 * g + 1], aH, bh1);
                MMA_BF16(sc[2 * g + 1], aH, bl1);
                MMA_BF16(sc[2 * g + 1], aL, bh1);
            }
        }

        if (kb + 63 > r0w) {
#pragma unroll
            for (int j = 0; j < 8; j++) {
                const int colg = kb + j * 8 + (lane & 3) * 2;
                if (colg     > r0w) sc[j][0] = -1e30f;
                if (colg + 1 > r0w) sc[j][1] = -1e30f;
                if (colg     > r1w) sc[j][2] = -1e30f;
                if (colg + 1 > r1w) sc[j][3] = -1e30f;
            }
        }

        float mx0 = -1e30f, mx1 = -1e30f;
#pragma unroll
        for (int j = 0; j < 8; j++) {
            mx0 = fmaxf(mx0, fmaxf(sc[j][0], sc[j][1]));
            mx1 = fmaxf(mx1, fmaxf(sc[j][2], sc[j][3]));
        }
        mx0 = fmaxf(mx0, __shfl_xor_sync(0xffffffff, mx0, 1));
        mx0 = fmaxf(mx0, __shfl_xor_sync(0xffffffff, mx0, 2));
        mx1 = fmaxf(mx1, __shfl_xor_sync(0xffffffff, mx1, 1));
        mx1 = fmaxf(mx1, __shfl_xor_sync(0xffffffff, mx1, 2));
        const float mn0 = fmaxf(m0, mx0), mn1 = fmaxf(m1, mx1);
        const float al0 = __expf(m0 - mn0), al1 = __expf(m1 - mn1);
        float rs0 = 0.f, rs1 = 0.f;
#pragma unroll
        for (int j = 0; j < 8; j++) {
            sc[j][0] = __expf(sc[j][0] - mn0);
            sc[j][1] = __expf(sc[j][1] - mn0);
            sc[j][2] = __expf(sc[j][2] - mn1);
            sc[j][3] = __expf(sc[j][3] - mn1);
            rs0 += sc[j][0] + sc[j][1];
            rs1 += sc[j][2] + sc[j][3];
        }
        rs0 += __shfl_xor_sync(0xffffffff, rs0, 1);
        rs0 += __shfl_xor_sync(0xffffffff, rs0, 2);
        rs1 += __shfl_xor_sync(0xffffffff, rs1, 1);
        rs1 += __shfl_xor_sync(0xffffffff, rs1, 2);
        l0 = l0 * al0 + rs0;
        l1 = l1 * al1 + rs1;
        m0 = mn0;
        m1 = mn1;
#pragma unroll
        for (int n = 0; n < 16; n++) {
            o_r[n][0] *= al0; o_r[n][1] *= al0;
            o_r[n][2] *= al1; o_r[n][3] *= al1;
        }

#pragma unroll
        for (int ku = 0; ku < 4; ku++) {
            float ph[8], pl[8];
#pragma unroll
            for (int e = 0; e < 4; e++) {
                const float v0 = sc[2 * ku][e], v1 = sc[2 * ku + 1][e];
                const float h0 = __bfloat162float(__float2bfloat16(v0));
                const float h1 = __bfloat162float(__float2bfloat16(v1));
                ph[e] = h0;     pl[e] = v0 - h0;
                ph[4 + e] = h1; pl[4 + e] = v1 - h1;
            }
            uint32_t aPh[4], aPl[4];
            aPh[0] = pack_bf2(ph[0], ph[1]);  aPl[0] = pack_bf2(pl[0], pl[1]);
            aPh[1] = pack_bf2(ph[2], ph[3]);  aPl[1] = pack_bf2(pl[2], pl[3]);
            aPh[2] = pack_bf2(ph[4], ph[5]);  aPl[2] = pack_bf2(pl[4], pl[5]);
            aPh[3] = pack_bf2(ph[6], ph[7]);  aPl[3] = pack_bf2(pl[6], pl[7]);
            const int vc = ku * 16 + xcol;
#pragma unroll
            for (int g = 0; g < 8; g++) {
                uint32_t rh[4], rl[4];
                LDMX4(rh, &sVh[(g * 16 + (lane & 15)) * VSTR + vc]);
                LDMX4(rl, &sVl[(g * 16 + (lane & 15)) * VSTR + vc]);
                uint32_t bh0[2] = {rh[0], rh[2]}, bh1[2] = {rh[1], rh[3]};
                uint32_t bl0[2] = {rl[0], rl[2]}, bl1[2] = {rl[1], rl[3]};
                MMA_BF16(o_r[2 * g],     aPh, bh0);
                MMA_BF16(o_r[2 * g],     aPh, bl0);
                MMA_BF16(o_r[2 * g],     aPl, bh0);
                MMA_BF16(o_r[2 * g + 1], aPh, bh1);
                MMA_BF16(o_r[2 * g + 1], aPh, bl1);
                MMA_BF16(o_r[2 * g + 1], aPl, bh1);
            }
        }
    }

    const float inv0 = 1.f / l0, inv1 = 1.f / l1;
#pragma unroll
    for (int n = 0; n < 16; n++) {
        const int col = h * HD + n * 8 + (lane & 3) * 2;
        outp[(size_t)r0w * (NH * HD) + col]     = o_r[n][0] * inv0;
        outp[(size_t)r0w * (NH * HD) + col + 1] = o_r[n][1] * inv0;
        outp[(size_t)r1w * (NH * HD) + col]     = o_r[n][2] * inv1;
        outp[(size_t)r1w * (NH * HD) + col + 1] = o_r[n][3] * inv1;
    }
}

// ---------------- launch ----------------
static inline void split_launch(const float* in, __nv_bfloat16* hi, __nv_bfloat16* lo, int n) {
    split_kernel<<<(n / 4 + 255) / 256, 256>>>(in, hi, lo, n);
}

extern "C" void kernel_launch(void* const* d_in, const int* in_sizes, int n_in,
                              void* d_out, int out_size) {
    const float* x          = (const float*)d_in[0];
    const float* cosp       = (const float*)d_in[1];
    const float* sinp       = (const float*)d_in[2];
    const float* q_a_w      = (const float*)d_in[3];
    const float* q_a_norm_w = (const float*)d_in[4];
    const float* q_b_w      = (const float*)d_in[5];
    const float* kv_a_w     = (const float*)d_in[6];
    const float* kv_a_norm_w= (const float*)d_in[7];
    const float* kv_b_w     = (const float*)d_in[8];
    const float* o_w        = (const float*)d_in[9];

    float *qlat, *q, *kv, *kvn, *kvup, *attn, *part;
    __nv_bfloat16 *xh, *xl, *ah, *al, *wh, *wl;
    __nv_bfloat16 *qbh, *qbl, *kbh, *kbl, *vbh, *vbl;
    cudaGetSymbolAddress((void**)&qlat, g_qlat);
    cudaGetSymbolAddress((void**)&q,    g_q);
    cudaGetSymbolAddress((void**)&kv,   g_kv);
    cudaGetSymbolAddress((void**)&kvn,  g_kvn);
    cudaGetSymbolAddress((void**)&kvup, g_kvup);
    cudaGetSymbolAddress((void**)&attn, g_attn);
    cudaGetSymbolAddress((void**)&part, g_part);
    cudaGetSymbolAddress((void**)&xh,   g_xh);
    cudaGetSymbolAddress((void**)&xl,   g_xl);
    cudaGetSymbolAddress((void**)&ah,   g_ah);
    cudaGetSymbolAddress((void**)&al,   g_al);
    cudaGetSymbolAddress((void**)&wh,   g_wh);
    cudaGetSymbolAddress((void**)&wl,   g_wl);
    cudaGetSymbolAddress((void**)&qbh,  g_qbh);
    cudaGetSymbolAddress((void**)&qbl,  g_qbl);
    cudaGetSymbolAddress((void**)&kbh,  g_kbh);
    cudaGetSymbolAddress((void**)&kbl,  g_kbl);
    cudaGetSymbolAddress((void**)&vbh,  g_vbh);
    cudaGetSymbolAddress((void**)&vbl,  g_vbl);

    cudaFuncSetAttribute(gemm_bf16x3, cudaFuncAttributeMaxDynamicSharedMemorySize, GEMM_SMEM);
    cudaFuncSetAttribute(attn_mma, cudaFuncAttributeMaxDynamicSharedMemorySize, ATTN_SMEM);

    split_launch(x, xh, xl, S_LEN * HID);

    // 1+4 fused, K-split 4) [qlat | kv] = x @ [q_a_w ; kv_a_w]^T  (N = 2496, Ksub = 1024)
    split_launch(q_a_w, wh, wl, QR * HID);
    split_launch(kv_a_w, wh + (size_t)QR * HID, wl + (size_t)QR * HID, (KVR + ROPE) * HID);
    gemm_bf16x3<<<dim3((NFUSE + 127) / 128, S_LEN / 128, 4), 256, GEMM_SMEM>>>(
        xh, xl, wh, wl, nullptr, 0, nullptr, 0, 0, part, S_LEN, NFUSE, HID);
    ksum4<<<(S_LEN * NFUSE / 4 + 255) / 256, 256>>>(part, qlat, QR, kv, KVR + ROPE, QR,
                                                    S_LEN, NFUSE);
    // 2) rmsnorm q_lat
    rmsnorm_kernel<<<S_LEN, 256>>>(qlat, q_a_norm_w, qlat, QR, QR, QR);
    // 5) rmsnorm kv -> kvn
    rmsnorm_kernel<<<S_LEN, 256>>>(kv, kv_a_norm_w, kvn, KVR, KVR + ROPE, KVR);
    // 3) q = q_lat @ q_b_w^T (direct write)
    split_launch(qlat, ah, al, S_LEN * QR);
    split_launch(q_b_w, wh, wl, NH * QDIM * QR);
    gemm_bf16x3<<<dim3((NH * QDIM) / 128, S_LEN / 128, 1), 256, GEMM_SMEM>>>(
        ah, al, wh, wl, q, NH * QDIM, q, NH * QDIM, NH * QDIM, nullptr, S_LEN, NH * QDIM, QR);
    // 6) kv_up = kvn @ kv_b_w^T (direct write)
    split_launch(kvn, ah, al, S_LEN * KVR);
    split_launch(kv_b_w, wh, wl, NH * 2 * HD * KVR);
    gemm_bf16x3<<<dim3((NH * 2 * HD) / 128, S_LEN / 128, 1), 256, GEMM_SMEM>>>(
        ah, al, wh, wl, kvup, NH * 2 * HD, kvup, NH * 2 * HD, NH * 2 * HD, nullptr,
        S_LEN, NH * 2 * HD, KVR);
    // 7) rope + packs
    rope_pack_bf16<<<dim3(S_LEN, NH), QDIM>>>(q, kv, kvup, cosp, sinp, qbh, qbl, kbh, kbl);
    v_pack<<<dim3(S_LEN / 32, HD / 32, NH), dim3(32, 8)>>>(kvup, vbh, vbl);
    // 8) attention
    attn_mma<<<dim3(S_LEN / 128, NH), 256, ATTN_SMEM>>>(qbh, qbl, kbh, kbl, vbh, vbl, attn);
    // 9) out = attn @ o_w^T (direct write, no K-split)
    split_launch(attn, ah, al, S_LEN * NH * HD);
    split_launch(o_w, wh, wl, HID * NH * HD);
    gemm_bf16x3<<<dim3(HID / 128, S_LEN / 128, 1), 256, GEMM_SMEM>>>(
        ah, al, wh, wl, (float*)d_out, HID, (float*)d_out, HID, HID, nullptr,
        S_LEN, HID, HID);
}

// round 17
// speedup vs baseline: 1.1725x; 1.0174x over previous
#include <cuda_runtime.h>
#include <cuda_bf16.h>
#include <cstdint>

#define S_LEN 2048
#define HID   4096
#define NH    32
#define HD    128
#define ROPE  64
#define QR    1536
#define KVR   896
#define QDIM  192
#define EPS   1e-6f
#define SCALE_F 0.07216878364870322f  // 1/sqrt(192)
#define NFUSE (QR + KVR + ROPE)       // 2496

// ---------------- scratch ----------------
__device__ float g_qlat[S_LEN * QR];
__device__ float g_q[S_LEN * NH * QDIM];
__device__ float g_kv[S_LEN * (KVR + ROPE)];
__device__ float g_kvn[S_LEN * KVR];
__device__ float g_kvup[S_LEN * NH * 2 * HD];
__device__ float g_attn[S_LEN * NH * HD];
__device__ float g_part[4 * (size_t)S_LEN * HID];   // 4 K-split slabs (134 MB, covers NFUSE & HID)

__device__ __nv_bfloat16 g_xh[S_LEN * HID];
__device__ __nv_bfloat16 g_xl[S_LEN * HID];
__device__ __nv_bfloat16 g_ah[S_LEN * HID];
__device__ __nv_bfloat16 g_al[S_LEN * HID];
__device__ __nv_bfloat16 g_wh[HID * HID];
__device__ __nv_bfloat16 g_wl[HID * HID];

__device__ __nv_bfloat16 g_qbh[(size_t)NH * S_LEN * QDIM];
__device__ __nv_bfloat16 g_qbl[(size_t)NH * S_LEN * QDIM];
__device__ __nv_bfloat16 g_kbh[(size_t)NH * S_LEN * QDIM];
__device__ __nv_bfloat16 g_kbl[(size_t)NH * S_LEN * QDIM];
__device__ __nv_bfloat16 g_vbh[(size_t)NH * HD * S_LEN];
__device__ __nv_bfloat16 g_vbl[(size_t)NH * HD * S_LEN];

// ---------------- helpers ----------------
#define MMA_BF16(c, a, b)                                                            \
    asm volatile(                                                                    \
        "mma.sync.aligned.m16n8k16.row.col.f32.bf16.bf16.f32 "                       \
        "{%0,%1,%2,%3}, {%4,%5,%6,%7}, {%8,%9}, {%0,%1,%2,%3};"                      \
        : "+f"(c[0]), "+f"(c[1]), "+f"(c[2]), "+f"(c[3])                             \
        : "r"(a[0]), "r"(a[1]), "r"(a[2]), "r"(a[3]), "r"(b[0]), "r"(b[1]))

#define LDMX4(r, p)                                                                  \
    asm volatile("ldmatrix.sync.aligned.m8n8.x4.shared.b16 {%0,%1,%2,%3}, [%4];"     \
                 : "=r"(r[0]), "=r"(r[1]), "=r"(r[2]), "=r"(r[3])                    \
                 : "r"((uint32_t)__cvta_generic_to_shared(p)))

#define LDMX2(r, p)                                                                  \
    asm volatile("ldmatrix.sync.aligned.m8n8.x2.shared.b16 {%0,%1}, [%2];"           \
                 : "=r"(r[0]), "=r"(r[1])                                            \
                 : "r"((uint32_t)__cvta_generic_to_shared(p)))

__device__ __forceinline__ void cp16(void* dst_smem, const void* src) {
    uint32_t d = (uint32_t)__cvta_generic_to_shared(dst_smem);
    asm volatile("cp.async.cg.shared.global [%0], [%1], 16;" :: "r"(d), "l"(src));
}
#define CP_COMMIT() asm volatile("cp.async.commit_group;" ::: "memory")
#define CP_WAIT(n)  asm volatile("cp.async.wait_group %0;" :: "n"(n) : "memory")

// ---------------- fp32 -> (bf16 hi, bf16 lo) split ----------------
__global__ void split_kernel(const float* __restrict__ in, __nv_bfloat16* __restrict__ hi,
                             __nv_bfloat16* __restrict__ lo, int n) {
    int i = (blockIdx.x * blockDim.x + threadIdx.x) * 4;
    if (i >= n) return;
    float4 v = *(const float4*)(in + i);
    float vv[4] = {v.x, v.y, v.z, v.w};
    __nv_bfloat16 h[4], l[4];
#pragma unroll
    for (int j = 0; j < 4; j++) {
        h[j] = __float2bfloat16(vv[j]);
        l[j] = __float2bfloat16(vv[j] - __bfloat162float(h[j]));
    }
    __nv_bfloat162* hp = (__nv_bfloat162*)(hi + i);
    __nv_bfloat162* lp = (__nv_bfloat162*)(lo + i);
    hp[0] = __halves2bfloat162(h[0], h[1]);
    hp[1] = __halves2bfloat162(h[2], h[3]);
    lp[0] = __halves2bfloat162(l[0], l[1]);
    lp[1] = __halves2bfloat162(l[2], l[3]);
}

// ---------------- split-bf16 GEMM (R8 exact core) + optional K-split ----------------
#define LDSB 40
#define ST_TILE (128 * LDSB)
#define GEMM_SMEM (2 * 4 * ST_TILE * 2)   // 80 KB -> 2 CTAs/SM

__global__ void __launch_bounds__(256, 2) gemm_bf16x3(
    const __nv_bfloat16* __restrict__ Ah, const __nv_bfloat16* __restrict__ Al,
    const __nv_bfloat16* __restrict__ Bh, const __nv_bfloat16* __restrict__ Bl,
    float* __restrict__ C1, int ld1, float* __restrict__ C2, int ld2, int n1,
    float* __restrict__ Cp, int M, int N, int K) {
    extern __shared__ __nv_bfloat16 smx[];
    const int tid = threadIdx.x;
    const int wid = tid >> 5, lane = tid & 31;
    const int bm = blockIdx.y * 128;
    const int bn = blockIdx.x * 128;
    const int wm = (wid >> 2) * 64;
    const int wn = (wid & 3) * 32;

    const int Ksub = K / gridDim.z;
    const int Koff = blockIdx.z * Ksub;

    const int lr = tid >> 1;
    const int lk = (tid & 1) * 16;
    const __nv_bfloat16* gAh = Ah + (size_t)(bm + lr) * K + Koff + lk;
    const __nv_bfloat16* gAl = Al + (size_t)(bm + lr) * K + Koff + lk;
    const int brow = min(bn + lr, N - 1);
    const __nv_bfloat16* gBh = Bh + (size_t)brow * K + Koff + lk;
    const __nv_bfloat16* gBl = Bl + (size_t)brow * K + Koff + lk;

    const int NS = Ksub / 32;
    const int soff = lr * LDSB + lk;

    auto load_stage = [&](int s) {
        __nv_bfloat16* buf = smx + (s & 1) * 4 * ST_TILE;
        const int k0 = s * 32;
        cp16(buf + soff,                    gAh + k0);
        cp16(buf + soff + 8,                gAh + k0 + 8);
        cp16(buf + ST_TILE + soff,          gAl + k0);
        cp16(buf + ST_TILE + soff + 8,      gAl + k0 + 8);
        cp16(buf + 2 * ST_TILE + soff,      gBh + k0);
        cp16(buf + 2 * ST_TILE + soff + 8,  gBh + k0 + 8);
        cp16(buf + 3 * ST_TILE + soff,      gBl + k0);
        cp16(buf + 3 * ST_TILE + soff + 8,  gBl + k0 + 8);
        CP_COMMIT();
    };

    float acc[4][4][4];
#pragma unroll
    for (int i = 0; i < 4; i++)
#pragma unroll
        for (int j = 0; j < 4; j++)
#pragma unroll
            for (int r = 0; r < 4; r++) acc[i][j][r] = 0.f;

    load_stage(0);
    CP_WAIT(0);
    __syncthreads();

    const int ar = wm + (lane & 15);
    const int ac = (lane >> 4) * 8;
    const int br = wn + (lane & 7);
    const int bc = ((lane >> 3) & 1) * 8;

    for (int s = 0; s < NS; s++) {
        if (s + 1 < NS) load_stage(s + 1);

        const __nv_bfloat16* buf = smx + (s & 1) * 4 * ST_TILE;
        const __nv_bfloat16* bAh = buf;
        const __nv_bfloat16* bAl = buf + ST_TILE;
        const __nv_bfloat16* bBh = buf + 2 * ST_TILE;
        const __nv_bfloat16* bBl = buf + 3 * ST_TILE;

#pragma unroll
        for (int kk = 0; kk < 32; kk += 16) {
            uint32_t a_h[4][4], a_l[4][4], b_h[4][2], b_l[4][2];
#pragma unroll
            for (int mi = 0; mi < 4; mi++) {
                LDMX4(a_h[mi], &bAh[(ar + mi * 16) * LDSB + kk + ac]);
                LDMX4(a_l[mi], &bAl[(ar + mi * 16) * LDSB + kk + ac]);
            }
#pragma unroll
            for (int nj = 0; nj < 4; nj++) {
                LDMX2(b_h[nj], &bBh[(br + nj * 8) * LDSB + kk + bc]);
                LDMX2(b_l[nj], &bBl[(br + nj * 8) * LDSB + kk + bc]);
            }
#pragma unroll
            for (int mi = 0; mi < 4; mi++)
#pragma unroll
                for (int nj = 0; nj < 4; nj++) MMA_BF16(acc[mi][nj], a_h[mi], b_h[nj]);
#pragma unroll
            for (int mi = 0; mi < 4; mi++)
#pragma unroll
                for (int nj = 0; nj < 4; nj++) MMA_BF16(acc[mi][nj], a_h[mi], b_l[nj]);
#pragma unroll
            for (int mi = 0; mi < 4; mi++)
#pragma unroll
                for (int nj = 0; nj < 4; nj++) MMA_BF16(acc[mi][nj], a_l[mi], b_h[nj]);
        }

        if (s + 1 < NS) {
            CP_WAIT(0);
            __syncthreads();
        }
    }

    if (gridDim.z > 1) {
        float* dst = Cp + (size_t)blockIdx.z * M * N;
#pragma unroll
        for (int mi = 0; mi < 4; mi++) {
#pragma unroll
            for (int nj = 0; nj < 4; nj++) {
                const int row0 = bm + wm + mi * 16 + (lane >> 2);
                const int col = bn + wn + nj * 8 + (lane & 3) * 2;
                if (col < N) {
                    dst[(size_t)row0 * N + col]           = acc[mi][nj][0];
                    dst[(size_t)row0 * N + col + 1]       = acc[mi][nj][1];
                    dst[(size_t)(row0 + 8) * N + col]     = acc[mi][nj][2];
                    dst[(size_t)(row0 + 8) * N + col + 1] = acc[mi][nj][3];
                }
            }
        }
        return;
    }

#pragma unroll
    for (int mi = 0; mi < 4; mi++) {
#pragma unroll
        for (int nj = 0; nj < 4; nj++) {
            const int row0 = bm + wm + mi * 16 + (lane >> 2);
            const int col = bn + wn + nj * 8 + (lane & 3) * 2;
            if (col < N) {
                if (col < n1) {
                    C1[(size_t)row0 * ld1 + col]           = acc[mi][nj][0];
                    C1[(size_t)row0 * ld1 + col + 1]       = acc[mi][nj][1];
                    C1[(size_t)(row0 + 8) * ld1 + col]     = acc[mi][nj][2];
                    C1[(size_t)(row0 + 8) * ld1 + col + 1] = acc[mi][nj][3];
                } else {
                    const int c2 = col - n1;
                    C2[(size_t)row0 * ld2 + c2]           = acc[mi][nj][0];
                    C2[(size_t)row0 * ld2 + c2 + 1]       = acc[mi][nj][1];
                    C2[(size_t)(row0 + 8) * ld2 + c2]     = acc[mi][nj][2];
                    C2[(size_t)(row0 + 8) * ld2 + c2 + 1] = acc[mi][nj][3];
                }
            }
        }
    }
}

// ---------------- merge four K-split slabs into split C ----------------
__global__ void ksum4(const float* __restrict__ p, float* __restrict__ C1, int ld1,
                      float* __restrict__ C2, int ld2, int n1, int M, int N) {
    int i = (blockIdx.x * blockDim.x + threadIdx.x) * 4;
    if (i >= M * N) return;
    const size_t S = (size_t)M * N;
    float4 a = *(const float4*)(p + i);
    float4 b = *(const float4*)(p + S + i);
    float4 c = *(const float4*)(p + 2 * S + i);
    float4 d = *(const float4*)(p + 3 * S + i);
    float4 v = make_float4((a.x + b.x) + (c.x + d.x), (a.y + b.y) + (c.y + d.y),
                           (a.z + b.z) + (c.z + d.z), (a.w + b.w) + (c.w + d.w));
    const int row = i / N, col = i % N;
    if (col < n1) *(float4*)(C1 + (size_t)row * ld1 + col) = v;
    else          *(float4*)(C2 + (size_t)row * ld2 + col - n1) = v;
}

// ---------------- RMSNorm ----------------
__global__ void rmsnorm_kernel(const float* __restrict__ in, const float* __restrict__ w,
                               float* __restrict__ out, int n, int in_stride, int out_stride) {
    const int row = blockIdx.x;
    const float* p = in + (size_t)row * in_stride;
    float ss = 0.f;
    for (int i = threadIdx.x; i < n; i += blockDim.x) {
        float v = p[i];
        ss += v * v;
    }
    __shared__ float red[8];
#pragma unroll
    for (int o = 16; o > 0; o >>= 1) ss += __shfl_xor_sync(0xffffffff, ss, o);
    if ((threadIdx.x & 31) == 0) red[threadIdx.x >> 5] = ss;
    __syncthreads();
    if (threadIdx.x < 8) {
        float v = red[threadIdx.x];
#pragma unroll
        for (int o = 4; o > 0; o >>= 1) v += __shfl_xor_sync(0xff, v, o);
        if (threadIdx.x == 0) red[0] = v;
    }
    __syncthreads();
    const float scale = rsqrtf(red[0] / (float)n + EPS);
    float* q = out + (size_t)row * out_stride;
    for (int i = threadIdx.x; i < n; i += blockDim.x) q[i] = p[i] * scale * w[i];
}

// ---------------- RoPE + pack Q/K bf16 hi/lo [h][s][d] ----------------
__global__ void rope_pack_bf16(const float* __restrict__ q, const float* __restrict__ kv,
                               const float* __restrict__ kvup,
                               const float* __restrict__ cosT, const float* __restrict__ sinT,
                               __nv_bfloat16* __restrict__ qh, __nv_bfloat16* __restrict__ ql,
                               __nv_bfloat16* __restrict__ kh, __nv_bfloat16* __restrict__ kl) {
    const int s = blockIdx.x;
    const int h = blockIdx.y;
    const int d = threadIdx.x;

    float qv, kvv;
    if (d < ROPE) {
        const float c = cosT[s * ROPE + d];
        const float sn = sinT[s * ROPE + d];
        const int dro = (d < 32) ? d + 32 : d - 32;
        const float sgn = (d < 32) ? -1.f : 1.f;
        const float xq = q[(size_t)s * (NH * QDIM) + h * QDIM + d];
        const float xqo = q[(size_t)s * (NH * QDIM) + h * QDIM + dro];
        qv = xq * c + sgn * xqo * sn;
        const float xk = kv[(size_t)s * (KVR + ROPE) + KVR + d];
        const float xko = kv[(size_t)s * (KVR + ROPE) + KVR + dro];
        kvv = xk * c + sgn * xko * sn;
    } else {
        qv = q[(size_t)s * (NH * QDIM) + h * QDIM + d];
        kvv = kvup[(size_t)s * (NH * 2 * HD) + h * (2 * HD) + (d - ROPE)];
    }
    qv *= SCALE_F;
    const size_t o = ((size_t)h * S_LEN + s) * QDIM + d;
    __nv_bfloat16 hq = __float2bfloat16(qv);
    qh[o] = hq;
    ql[o] = __float2bfloat16(qv - __bfloat162float(hq));
    __nv_bfloat16 hk = __float2bfloat16(kvv);
    kh[o] = hk;
    kl[o] = __float2bfloat16(kvv - __bfloat162float(hk));
}

// ---------------- V transpose-pack ----------------
__global__ void v_pack(const float* __restrict__ kvup,
                       __nv_bfloat16* __restrict__ vh, __nv_bfloat16* __restrict__ vl) {
    __shared__ float tile[32][33];
    const int s0 = blockIdx.x * 32, d0 = blockIdx.y * 32, h = blockIdx.z;
    const int tx = threadIdx.x, ty = threadIdx.y;
#pragma unroll
    for (int i = 0; i < 4; i++) {
        const int s = s0 + ty + i * 8;
        tile[ty + i * 8][tx] = kvup[(size_t)s * (NH * 2 * HD) + h * (2 * HD) + HD + d0 + tx];
    }
    __syncthreads();
#pragma unroll
    for (int i = 0; i < 4; i++) {
        const int dv = d0 + ty + i * 8;
        const float v = tile[tx][ty + i * 8];
        __nv_bfloat16 hv = __float2bfloat16(v);
        const size_t o = ((size_t)(h * HD + dv)) * S_LEN + s0 + tx;
        vh[o] = hv;
        vl[o] = __float2bfloat16(v - __bfloat162float(hv));
    }
}

// ---------------- tensor-core flash attention (validated R5/R8) ----------------
#define QSTR 200
#define VSTR 72
#define ATTN_SMEM ((128 * QSTR * 2 + 64 * QSTR * 2 + 128 * VSTR * 2) * 2)

__device__ __forceinline__ uint32_t pack_bf2(float a, float b) {
    __nv_bfloat162 t = __floats2bfloat162_rn(a, b);
    return *(uint32_t*)&t;
}

__global__ void __launch_bounds__(256) attn_mma(
    const __nv_bfloat16* __restrict__ qh, const __nv_bfloat16* __restrict__ ql,
    const __nv_bfloat16* __restrict__ kh, const __nv_bfloat16* __restrict__ kl,
    const __nv_bfloat16* __restrict__ vh, const __nv_bfloat16* __restrict__ vl,
    float* __restrict__ outp) {
    extern __shared__ __nv_bfloat16 sm[];
    __nv_bfloat16* sQh = sm;
    __nv_bfloat16* sQl = sQh + 128 * QSTR;
    __nv_bfloat16* sKh = sQl + 128 * QSTR;
    __nv_bfloat16* sKl = sKh + 64 * QSTR;
    __nv_bfloat16* sVh = sKl + 64 * QSTR;
    __nv_bfloat16* sVl = sVh + 128 * VSTR;

    const int qb = (gridDim.x - 1 - blockIdx.x) * 128;
    const int h = blockIdx.y;
    const int tid = threadIdx.x;
    const int wid = tid >> 5, lane = tid & 31;

    const __nv_bfloat16* qhb = qh + ((size_t)h * S_LEN + qb) * QDIM;
    const __nv_bfloat16* qlb = ql + ((size_t)h * S_LEN + qb) * QDIM;
    for (int i = tid; i < 128 * 24; i += 256) {
        const int r = i / 24, c = (i % 24) * 8;
        *(uint4*)&sQh[r * QSTR + c] = *(const uint4*)&qhb[(size_t)r * QDIM + c];
        *(uint4*)&sQl[r * QSTR + c] = *(const uint4*)&qlb[(size_t)r * QDIM + c];
    }

    float o_r[16][4];
#pragma unroll
    for (int n = 0; n < 16; n++)
#pragma unroll
        for (int r = 0; r < 4; r++) o_r[n][r] = 0.f;
    float m0 = -1e30f, m1 = -1e30f, l0 = 0.f, l1 = 0.f;

    const int r0w = qb + wid * 16 + (lane >> 2);
    const int r1w = r0w + 8;

    const __nv_bfloat16* khb = kh + (size_t)h * S_LEN * QDIM;
    const __nv_bfloat16* klb = kl + (size_t)h * S_LEN * QDIM;
    const __nv_bfloat16* vhb = vh + (size_t)h * HD * S_LEN;
    const __nv_bfloat16* vlb = vl + (size_t)h * HD * S_LEN;

    const int ntiles = qb / 64 + 2;
    for (int t = 0; t < ntiles; t++) {
        const int kb = t * 64;
        __syncthreads();
        for (int i = tid; i < 64 * 24; i += 256) {
            const int r = i / 24, c = (i % 24) * 8;
            *(uint4*)&sKh[r * QSTR + c] = *(const uint4*)&khb[(size_t)(kb + r) * QDIM + c];
            *(uint4*)&sKl[r * QSTR + c] = *(const uint4*)&klb[(size_t)(kb + r) * QDIM + c];
        }
        for (int i = tid; i < 128 * 8; i += 256) {
            const int r = i / 8, c = (i % 8) * 8;
            *(uint4*)&sVh[r * VSTR + c] = *(const uint4*)&vhb[(size_t)r * S_LEN + kb + c];
            *(uint4*)&sVl[r * VSTR + c] = *(const uint4*)&vlb[(size_t)r * S_LEN + kb + c];
        }
        __syncthreads();

        if (kb > qb + wid * 16 + 15) continue;

        float sc[8][4];
#pragma unroll
        for (int j = 0; j < 8; j++)
#pragma unroll
            for (int r = 0; r < 4; r++) sc[j][r] = 0.f;

        const int arow = wid * 16 + (lane & 15);
        const int xcol = (lane >> 4) * 8;
#pragma unroll
        for (int ks = 0; ks < 12; ks++) {
            uint32_t aH[4], aL[4];
            LDMX4(aH, &sQh[arow * QSTR + ks * 16 + xcol]);
            LDMX4(aL, &sQl[arow * QSTR + ks * 16 + xcol]);
#pragma unroll
            for (int g = 0; g < 4; g++) {
                uint32_t rh[4], rl[4];
                LDMX4(rh, &sKh[(g * 16 + (lane & 15)) * QSTR + ks * 16 + xcol]);
                LDMX4(rl, &sKl[(g * 16 + (lane & 15)) * QSTR + ks * 16 + xcol]);
                uint32_t bh0[2] = {rh[0], rh[2]}, bh1[2] = {rh[1], rh[3]};
                uint32_t bl0[2] = {rl[0], rl[2]}, bl1[2] = {rl[1], rl[3]};
                MMA_BF16(sc[2 * g],     aH, bh0);
                MMA_BF16(sc[2 * g],     aH, bl0);
                MMA_BF16(sc[2 * g],     aL, bh0);
                MMA_BF16(sc[2 * g + 1], aH, bh1);
                MMA_BF16(sc[2 * g + 1], aH, bl1);
                MMA_BF16(sc[2 * g + 1], aL, bh1);
            }
        }

        if (kb + 63 > r0w) {
#pragma unroll
            for (int j = 0; j < 8; j++) {
                const int colg = kb + j * 8 + (lane & 3) * 2;
                if (colg     > r0w) sc[j][0] = -1e30f;
                if (colg + 1 > r0w) sc[j][1] = -1e30f;
                if (colg     > r1w) sc[j][2] = -1e30f;
                if (colg + 1 > r1w) sc[j][3] = -1e30f;
            }
        }

        float mx0 = -1e30f, mx1 = -1e30f;
#pragma unroll
        for (int j = 0; j < 8; j++) {
            mx0 = fmaxf(mx0, fmaxf(sc[j][0], sc[j][1]));
            mx1 = fmaxf(mx1, fmaxf(sc[j][2], sc[j][3]));
        }
        mx0 = fmaxf(mx0, __shfl_xor_sync(0xffffffff, mx0, 1));
        mx0 = fmaxf(mx0, __shfl_xor_sync(0xffffffff, mx0, 2));
        mx1 = fmaxf(mx1, __shfl_xor_sync(0xffffffff, mx1, 1));
        mx1 = fmaxf(mx1, __shfl_xor_sync(0xffffffff, mx1, 2));
        const float mn0 = fmaxf(m0, mx0), mn1 = fmaxf(m1, mx1);
        const float al0 = __expf(m0 - mn0), al1 = __expf(m1 - mn1);
        float rs0 = 0.f, rs1 = 0.f;
#pragma unroll
        for (int j = 0; j < 8; j++) {
            sc[j][0] = __expf(sc[j][0] - mn0);
            sc[j][1] = __expf(sc[j][1] - mn0);
            sc[j][2] = __expf(sc[j][2] - mn1);
            sc[j][3] = __expf(sc[j][3] - mn1);
            rs0 += sc[j][0] + sc[j][1];
            rs1 += sc[j][2] + sc[j][3];
        }
        rs0 += __shfl_xor_sync(0xffffffff, rs0, 1);
        rs0 += __shfl_xor_sync(0xffffffff, rs0, 2);
        rs1 += __shfl_xor_sync(0xffffffff, rs1, 1);
        rs1 += __shfl_xor_sync(0xffffffff, rs1, 2);
        l0 = l0 * al0 + rs0;
        l1 = l1 * al1 + rs1;
        m0 = mn0;
        m1 = mn1;
#pragma unroll
        for (int n = 0; n < 16; n++) {
            o_r[n][0] *= al0; o_r[n][1] *= al0;
            o_r[n][2] *= al1; o_r[n][3] *= al1;
        }

#pragma unroll
        for (int ku = 0; ku < 4; ku++) {
            float ph[8], pl[8];
#pragma unroll
            for (int e = 0; e < 4; e++) {
                const float v0 = sc[2 * ku][e], v1 = sc[2 * ku + 1][e];
                const float h0 = __bfloat162float(__float2bfloat16(v0));
                const float h1 = __bfloat162float(__float2bfloat16(v1));
                ph[e] = h0;     pl[e] = v0 - h0;
                ph[4 + e] = h1; pl[4 + e] = v1 - h1;
            }
            uint32_t aPh[4], aPl[4];
            aPh[0] = pack_bf2(ph[0], ph[1]);  aPl[0] = pack_bf2(pl[0], pl[1]);
            aPh[1] = pack_bf2(ph[2], ph[3]);  aPl[1] = pack_bf2(pl[2], pl[3]);
            aPh[2] = pack_bf2(ph[4], ph[5]);  aPl[2] = pack_bf2(pl[4], pl[5]);
            aPh[3] = pack_bf2(ph[6], ph[7]);  aPl[3] = pack_bf2(pl[6], pl[7]);
            const int vc = ku * 16 + xcol;
#pragma unroll
            for (int g = 0; g < 8; g++) {
                uint32_t rh[4], rl[4];
                LDMX4(rh, &sVh[(g * 16 + (lane & 15)) * VSTR + vc]);
                LDMX4(rl, &sVl[(g * 16 + (lane & 15)) * VSTR + vc]);
                uint32_t bh0[2] = {rh[0], rh[2]}, bh1[2] = {rh[1], rh[3]};
                uint32_t bl0[2] = {rl[0], rl[2]}, bl1[2] = {rl[1], rl[3]};
                MMA_BF16(o_r[2 * g],     aPh, bh0);
                MMA_BF16(o_r[2 * g],     aPh, bl0);
                MMA_BF16(o_r[2 * g],     aPl, bh0);
                MMA_BF16(o_r[2 * g + 1], aPh, bh1);
                MMA_BF16(o_r[2 * g + 1], aPh, bl1);
                MMA_BF16(o_r[2 * g + 1], aPl, bh1);
            }
        }
    }

    const float inv0 = 1.f / l0, inv1 = 1.f / l1;
#pragma unroll
    for (int n = 0; n < 16; n++) {
        const int col = h * HD + n * 8 + (lane & 3) * 2;
        outp[(size_t)r0w * (NH * HD) + col]     = o_r[n][0] * inv0;
        outp[(size_t)r0w * (NH * HD) + col + 1] = o_r[n][1] * inv0;
        outp[(size_t)r1w * (NH * HD) + col]     = o_r[n][2] * inv1;
        outp[(size_t)r1w * (NH * HD) + col + 1] = o_r[n][3] * inv1;
    }
}

// ---------------- launch ----------------
static inline void split_launch(const float* in, __nv_bfloat16* hi, __nv_bfloat16* lo, int n) {
    split_kernel<<<(n / 4 + 255) / 256, 256>>>(in, hi, lo, n);
}

extern "C" void kernel_launch(void* const* d_in, const int* in_sizes, int n_in,
                              void* d_out, int out_size) {
    const float* x          = (const float*)d_in[0];
    const float* cosp       = (const float*)d_in[1];
    const float* sinp       = (const float*)d_in[2];
    const float* q_a_w      = (const float*)d_in[3];
    const float* q_a_norm_w = (const float*)d_in[4];
    const float* q_b_w      = (const float*)d_in[5];
    const float* kv_a_w     = (const float*)d_in[6];
    const float* kv_a_norm_w= (const float*)d_in[7];
    const float* kv_b_w     = (const float*)d_in[8];
    const float* o_w        = (const float*)d_in[9];

    float *qlat, *q, *kv, *kvn, *kvup, *attn, *part;
    __nv_bfloat16 *xh, *xl, *ah, *al, *wh, *wl;
    __nv_bfloat16 *qbh, *qbl, *kbh, *kbl, *vbh, *vbl;
    cudaGetSymbolAddress((void**)&qlat, g_qlat);
    cudaGetSymbolAddress((void**)&q,    g_q);
    cudaGetSymbolAddress((void**)&kv,   g_kv);
    cudaGetSymbolAddress((void**)&kvn,  g_kvn);
    cudaGetSymbolAddress((void**)&kvup, g_kvup);
    cudaGetSymbolAddress((void**)&attn, g_attn);
    cudaGetSymbolAddress((void**)&part, g_part);
    cudaGetSymbolAddress((void**)&xh,   g_xh);
    cudaGetSymbolAddress((void**)&xl,   g_xl);
    cudaGetSymbolAddress((void**)&ah,   g_ah);
    cudaGetSymbolAddress((void**)&al,   g_al);
    cudaGetSymbolAddress((void**)&wh,   g_wh);
    cudaGetSymbolAddress((void**)&wl,   g_wl);
    cudaGetSymbolAddress((void**)&qbh,  g_qbh);
    cudaGetSymbolAddress((void**)&qbl,  g_qbl);
    cudaGetSymbolAddress((void**)&kbh,  g_kbh);
    cudaGetSymbolAddress((void**)&kbl,  g_kbl);
    cudaGetSymbolAddress((void**)&vbh,  g_vbh);
    cudaGetSymbolAddress((void**)&vbl,  g_vbl);

    cudaFuncSetAttribute(gemm_bf16x3, cudaFuncAttributeMaxDynamicSharedMemorySize, GEMM_SMEM);
    cudaFuncSetAttribute(attn_mma, cudaFuncAttributeMaxDynamicSharedMemorySize, ATTN_SMEM);

    split_launch(x, xh, xl, S_LEN * HID);

    // 1+4 fused, K-split 4) [qlat | kv] = x @ [q_a_w ; kv_a_w]^T  (N = 2496, Ksub = 1024)
    split_launch(q_a_w, wh, wl, QR * HID);
    split_launch(kv_a_w, wh + (size_t)QR * HID, wl + (size_t)QR * HID, (KVR + ROPE) * HID);
    gemm_bf16x3<<<dim3((NFUSE + 127) / 128, S_LEN / 128, 4), 256, GEMM_SMEM>>>(
        xh, xl, wh, wl, nullptr, 0, nullptr, 0, 0, part, S_LEN, NFUSE, HID);
    ksum4<<<(S_LEN * NFUSE / 4 + 255) / 256, 256>>>(part, qlat, QR, kv, KVR + ROPE, QR,
                                                    S_LEN, NFUSE);
    // 2) rmsnorm q_lat
    rmsnorm_kernel<<<S_LEN, 256>>>(qlat, q_a_norm_w, qlat, QR, QR, QR);
    // 5) rmsnorm kv -> kvn
    rmsnorm_kernel<<<S_LEN, 256>>>(kv, kv_a_norm_w, kvn, KVR, KVR + ROPE, KVR);
    // 3) q = q_lat @ q_b_w^T (direct write)
    split_launch(qlat, ah, al, S_LEN * QR);
    split_launch(q_b_w, wh, wl, NH * QDIM * QR);
    gemm_bf16x3<<<dim3((NH * QDIM) / 128, S_LEN / 128, 1), 256, GEMM_SMEM>>>(
        ah, al, wh, wl, q, NH * QDIM, q, NH * QDIM, NH * QDIM, nullptr, S_LEN, NH * QDIM, QR);
    // 6) kv_up = kvn @ kv_b_w^T (direct write)
    split_launch(kvn, ah, al, S_LEN * KVR);
    split_launch(kv_b_w, wh, wl, NH * 2 * HD * KVR);
    gemm_bf16x3<<<dim3((NH * 2 * HD) / 128, S_LEN / 128, 1), 256, GEMM_SMEM>>>(
        ah, al, wh, wl, kvup, NH * 2 * HD, kvup, NH * 2 * HD, NH * 2 * HD, nullptr,
        S_LEN, NH * 2 * HD, KVR);
    // 7) rope + packs
    rope_pack_bf16<<<dim3(S_LEN, NH), QDIM>>>(q, kv, kvup, cosp, sinp, qbh, qbl, kbh, kbl);
    v_pack<<<dim3(S_LEN / 32, HD / 32, NH), dim3(32, 8)>>>(kvup, vbh, vbl);
    // 8) attention
    attn_mma<<<dim3(S_LEN / 128, NH), 256, ATTN_SMEM>>>(qbh, qbl, kbh, kbl, vbh, vbl, attn);
    // 9) out = attn @ o_w^T, K-split 4 (Ksub = 1024, 2048 CTAs -> 7 waves x T/4)
    split_launch(attn, ah, al, S_LEN * NH * HD);
    split_launch(o_w, wh, wl, HID * NH * HD);
    gemm_bf16x3<<<dim3(HID / 128, S_LEN / 128, 4), 256, GEMM_SMEM>>>(
        ah, al, wh, wl, nullptr, 0, nullptr, 0, 0, part, S_LEN, HID, HID);
    ksum4<<<(S_LEN * HID / 4 + 255) / 256, 256>>>(part, (float*)d_out, HID, (float*)d_out, HID,
                                                  HID, S_LEN, HID);
}